// round 12
// baseline (speedup 1.0000x reference)
#include <cuda_runtime.h>
#include <cuda_bf16.h>
#include <cstdint>

// Problem constants
static constexpr int B  = 2;
static constexpr int S  = 2048;
static constexpr int D  = 1024;
static constexpr int H  = 16;
static constexpr int DK = 64;
static constexpr int M  = B * S;   // 4096

// ---------------------------------------------------------------------------
// Device scratch
// ---------------------------------------------------------------------------
__device__ __nv_bfloat16 g_qhi[(size_t)B * H * S * DK];
__device__ __nv_bfloat16 g_qlo[(size_t)B * H * S * DK];
__device__ __nv_bfloat16 g_khi[(size_t)B * H * S * DK];
__device__ __nv_bfloat16 g_klo[(size_t)B * H * S * DK];
__device__ __nv_bfloat16 g_vhi[(size_t)B * H * S * DK];
__device__ __nv_bfloat16 g_vlo[(size_t)B * H * S * DK];

// out-projection A operand (written by attention epilogue), [M, D]
__device__ __nv_bfloat16 g_Ahi[(size_t)M * D];
__device__ __nv_bfloat16 g_Alo[(size_t)M * D];
// W transposed [N,K], slots 0..3 = Wq,Wk,Wv,Wo
__device__ __nv_bfloat16 g_Bhi[4 * (size_t)D * D];
__device__ __nv_bfloat16 g_Blo[4 * (size_t)D * D];

// ---------------------------------------------------------------------------
// PTX helpers
// ---------------------------------------------------------------------------
__device__ __forceinline__ uint32_t smem_u32(const void* p) {
    uint32_t a;
    asm("{ .reg .u64 t; cvta.to.shared.u64 t, %1; cvt.u32.u64 %0, t; }"
        : "=r"(a) : "l"(p));
    return a;
}
__device__ __forceinline__ void cp16(uint32_t saddr, const void* g) {
    asm volatile("cp.async.cg.shared.global [%0], [%1], 16;"
                 :: "r"(saddr), "l"(g) : "memory");
}
__device__ __forceinline__ void cp_commit() {
    asm volatile("cp.async.commit_group;" ::: "memory");
}
template <int N>
__device__ __forceinline__ void cp_wait() {
    asm volatile("cp.async.wait_group %0;" :: "n"(N) : "memory");
}
__device__ __forceinline__ void ldm_x4(uint32_t& r0, uint32_t& r1,
                                       uint32_t& r2, uint32_t& r3, uint32_t a) {
    asm volatile("ldmatrix.sync.aligned.m8n8.x4.shared.b16 {%0,%1,%2,%3}, [%4];"
                 : "=r"(r0), "=r"(r1), "=r"(r2), "=r"(r3) : "r"(a));
}
__device__ __forceinline__ void ldm_x4_t(uint32_t& r0, uint32_t& r1,
                                         uint32_t& r2, uint32_t& r3, uint32_t a) {
    asm volatile("ldmatrix.sync.aligned.m8n8.x4.trans.shared.b16 {%0,%1,%2,%3}, [%4];"
                 : "=r"(r0), "=r"(r1), "=r"(r2), "=r"(r3) : "r"(a));
}
__device__ __forceinline__ void mma_16816(float& c0, float& c1, float& c2, float& c3,
                                          uint32_t a0, uint32_t a1, uint32_t a2,
                                          uint32_t a3, uint32_t b0, uint32_t b1) {
    asm volatile(
        "mma.sync.aligned.m16n8k16.row.col.f32.bf16.bf16.f32 "
        "{%0,%1,%2,%3}, {%4,%5,%6,%7}, {%8,%9}, {%0,%1,%2,%3};"
        : "+f"(c0), "+f"(c1), "+f"(c2), "+f"(c3)
        : "r"(a0), "r"(a1), "r"(a2), "r"(a3), "r"(b0), "r"(b1));
}

// ---------------------------------------------------------------------------
// Weight transpose + split: Wt[n][k] = W[k][n]  (small; kept as a kernel)
// ---------------------------------------------------------------------------
__global__ void convert_w_kernel(const float* __restrict__ w0,
                                 const float* __restrict__ w1,
                                 const float* __restrict__ w2,
                                 const float* __restrict__ w3)
{
    __shared__ float t[32][33];
    const int z = blockIdx.z;
    const float* W = z == 0 ? w0 : z == 1 ? w1 : z == 2 ? w2 : w3;
    const size_t base = (size_t)z * D * D;
    const int n0 = blockIdx.x * 32, k0 = blockIdx.y * 32;

    for (int i = threadIdx.y; i < 32; i += 8)
        t[i][threadIdx.x] = W[(size_t)(k0 + i) * D + n0 + threadIdx.x];
    __syncthreads();
    for (int i = threadIdx.y; i < 32; i += 8) {
        float x = t[threadIdx.x][i];
        __nv_bfloat16 h = __float2bfloat16(x);
        size_t o = base + (size_t)(n0 + i) * D + k0 + threadIdx.x;
        g_Bhi[o] = h;
        g_Blo[o] = __float2bfloat16(x - __bfloat162float(h));
    }
}

// ---------------------------------------------------------------------------
// bf16 mma.sync GEMM, 3-term split (R6/R11 compute body).
// CTA 128x128, BK=64, 8 warps (64x32 tiles), 2-stage pipeline.
// MODE 0: A loaded as raw fp32 (Q/K/V inputs), split hi/lo IN-KERNEL in smem.
//         Epilogue scatters bf16 hi/lo q/k/v to [B,H,S,DK].
// MODE 1: A from g_Ahi/g_Alo bf16 (attention output); epilogue +bias fp32 out.
// ---------------------------------------------------------------------------
static constexpr int GBM = 128, GBN = 128, GBK = 64;
static constexpr int NC = D / GBK;                 // 16 chunks
static constexpr int RSTRIDE = 144;                // 128B data + 16B pad
static constexpr int TILE_B  = 128 * RSTRIDE;      // 18432
static constexpr int OA_HI = 0, OA_LO = TILE_B, OB_HI = 2 * TILE_B, OB_LO = 3 * TILE_B;
static constexpr int STG = 4 * TILE_B;             // 73728 per stage
static constexpr int FOFF = 2 * STG;               // 147456: fp32 A staging
static constexpr int FSTRIDE = 272;                // 256B data + 16B pad
static constexpr int FTILE = 128 * FSTRIDE;        // 34816 per stage
static constexpr int GEMM_SMEM0 = FOFF + 2 * FTILE;  // 217088 (MODE 0)
static constexpr int GEMM_SMEM1 = 2 * STG;           // 147456 (MODE 1)

// load one 128x64 bf16 tile (1024 cp16 units)
__device__ __forceinline__ void load_tile(const __nv_bfloat16* __restrict__ src,
                                          int row0, int k0, uint32_t sdst, int tid)
{
    #pragma unroll
    for (int i = 0; i < 4; i++) {
        int unit = tid + 256 * i;
        int r = unit >> 3, c = unit & 7;
        cp16(sdst + r * RSTRIDE + c * 16,
             src + (size_t)(row0 + r) * D + k0 + c * 8);
    }
}

// load one 128x64 fp32 tile (2048 cp16 units)
__device__ __forceinline__ void load_ftile(const float* __restrict__ src,
                                           int row0, int k0, uint32_t sdst, int tid)
{
    #pragma unroll
    for (int i = 0; i < 8; i++) {
        int unit = tid + 256 * i;
        int r = unit >> 4, c = unit & 15;
        cp16(sdst + r * FSTRIDE + c * 16,
             src + (size_t)(row0 + r) * D + k0 + c * 4);
    }
}

template <int MODE>
__global__ __launch_bounds__(256, 1) void tc_gemm_kernel(
    const float* __restrict__ a0, const float* __restrict__ a1,
    const float* __restrict__ a2,
    float* __restrict__ out_param, const float* __restrict__ bias)
{
    extern __shared__ char smc[];
    const uint32_t sb = smem_u32(smc);
    const int tid = threadIdx.x;
    const int lane = tid & 31, wid = tid >> 5;
    const int z = blockIdx.z;
    const int bm = blockIdx.y * GBM;
    const int bn = blockIdx.x * GBN;

    const float* Af = (MODE == 0) ? (z == 0 ? a0 : z == 1 ? a1 : a2) : nullptr;
    const __nv_bfloat16* Bhi = g_Bhi + (MODE == 0 ? (size_t)z * D * D : (size_t)3 * D * D);
    const __nv_bfloat16* Blo = g_Blo + (MODE == 0 ? (size_t)z * D * D : (size_t)3 * D * D);

    const int m_warp = (wid & 1) * 64;
    const int n_warp = (wid >> 1) * 32;

    const uint32_t a_lane = (uint32_t)((lane & 15) * RSTRIDE + ((lane >> 4) & 1) * 16);
    const uint32_t b_lane = (uint32_t)((((lane >> 4) & 1) * 8 + (lane & 7)) * RSTRIDE
                                       + ((lane >> 3) & 1) * 16);

    float acc[4][4][4];
    #pragma unroll
    for (int i = 0; i < 4; i++)
        #pragma unroll
        for (int j = 0; j < 4; j++)
            #pragma unroll
            for (int e = 0; e < 4; e++) acc[i][j][e] = 0.f;

    // prologue: chunk 0 -> stage 0
    if (MODE == 0) {
        load_ftile(Af, bm, 0, sb + FOFF, tid);
    } else {
        load_tile(g_Ahi, bm, 0, sb + OA_HI, tid);
        load_tile(g_Alo, bm, 0, sb + OA_LO, tid);
    }
    load_tile(Bhi, bn, 0, sb + OB_HI, tid);
    load_tile(Blo, bn, 0, sb + OB_LO, tid);
    cp_commit();

    for (int c = 0; c < NC; c++) {
        const int s = c & 1;
        if (c + 1 < NC) {
            const int k0 = (c + 1) * GBK;
            const uint32_t nb = sb + (s ^ 1) * STG;
            if (MODE == 0) {
                load_ftile(Af, bm, k0, sb + FOFF + (s ^ 1) * FTILE, tid);
            } else {
                load_tile(g_Ahi, bm, k0, nb + OA_HI, tid);
                load_tile(g_Alo, bm, k0, nb + OA_LO, tid);
            }
            load_tile(Bhi, bn, k0, nb + OB_HI, tid);
            load_tile(Blo, bn, k0, nb + OB_LO, tid);
            cp_commit();
            cp_wait<1>();
        } else {
            cp_wait<0>();
        }
        __syncthreads();

        const uint32_t stg = sb + s * STG;

        if (MODE == 0) {
            // split fp32 stage s -> bf16 hi/lo A tiles of stage s
            char* fsrc = smc + FOFF + s * FTILE;
            char* dhi  = smc + s * STG + OA_HI;
            char* dlo  = smc + s * STG + OA_LO;
            #pragma unroll
            for (int v = 0; v < 4; v++) {
                int u = tid + 256 * v;
                int r = u >> 3, cc = u & 7;
                const float4 x0 = *(const float4*)(fsrc + r * FSTRIDE + cc * 32);
                const float4 x1 = *(const float4*)(fsrc + r * FSTRIDE + cc * 32 + 16);
                float xs[8] = {x0.x, x0.y, x0.z, x0.w, x1.x, x1.y, x1.z, x1.w};
                uint32_t hw[4], lw[4];
                #pragma unroll
                for (int jj = 0; jj < 4; jj++) {
                    float p0 = xs[2 * jj], p1 = xs[2 * jj + 1];
                    __nv_bfloat162 h2 = __float22bfloat162_rn(make_float2(p0, p1));
                    float2 hf = __bfloat1622float2(h2);
                    __nv_bfloat162 l2 = __float22bfloat162_rn(
                        make_float2(p0 - hf.x, p1 - hf.y));
                    hw[jj] = *(uint32_t*)&h2;
                    lw[jj] = *(uint32_t*)&l2;
                }
                *(uint4*)(dhi + r * RSTRIDE + cc * 16) =
                    make_uint4(hw[0], hw[1], hw[2], hw[3]);
                *(uint4*)(dlo + r * RSTRIDE + cc * 16) =
                    make_uint4(lw[0], lw[1], lw[2], lw[3]);
            }
            __syncthreads();
        }

        #pragma unroll
        for (int t = 0; t < 4; t++) {
            uint32_t ah[4][4], al[4][4];
            #pragma unroll
            for (int i = 0; i < 4; i++) {
                const uint32_t ro = (uint32_t)((m_warp + i * 16) * RSTRIDE + t * 32) + a_lane;
                ldm_x4(ah[i][0], ah[i][1], ah[i][2], ah[i][3], stg + OA_HI + ro);
                ldm_x4(al[i][0], al[i][1], al[i][2], al[i][3], stg + OA_LO + ro);
            }
            uint32_t bh[8], bl[8];
            #pragma unroll
            for (int p = 0; p < 2; p++) {
                const uint32_t ro = (uint32_t)((n_warp + p * 16) * RSTRIDE + t * 32) + b_lane;
                ldm_x4(bh[p * 4 + 0], bh[p * 4 + 1], bh[p * 4 + 2], bh[p * 4 + 3],
                       stg + OB_HI + ro);
                ldm_x4(bl[p * 4 + 0], bl[p * 4 + 1], bl[p * 4 + 2], bl[p * 4 + 3],
                       stg + OB_LO + ro);
            }
            #pragma unroll
            for (int i = 0; i < 4; i++)
                #pragma unroll
                for (int j = 0; j < 4; j++) {
                    const int bi = (j >> 1) * 4 + (j & 1) * 2;
                    mma_16816(acc[i][j][0], acc[i][j][1], acc[i][j][2], acc[i][j][3],
                              ah[i][0], ah[i][1], ah[i][2], ah[i][3],
                              bh[bi], bh[bi + 1]);
                    mma_16816(acc[i][j][0], acc[i][j][1], acc[i][j][2], acc[i][j][3],
                              ah[i][0], ah[i][1], ah[i][2], ah[i][3],
                              bl[bi], bl[bi + 1]);
                    mma_16816(acc[i][j][0], acc[i][j][1], acc[i][j][2], acc[i][j][3],
                              al[i][0], al[i][1], al[i][2], al[i][3],
                              bh[bi], bh[bi + 1]);
                }
        }
        __syncthreads();
    }

    // Epilogue
    const int g = lane >> 2, tq = lane & 3;
    #pragma unroll
    for (int i = 0; i < 4; i++) {
        #pragma unroll
        for (int j = 0; j < 4; j++) {
            const int n = bn + n_warp + j * 8 + tq * 2;
            #pragma unroll
            for (int half = 0; half < 2; half++) {
                const int m = bm + m_warp + i * 16 + g + half * 8;
                float2 v = make_float2(acc[i][j][half * 2], acc[i][j][half * 2 + 1]);
                if (MODE == 0) {
                    __nv_bfloat16* dhi = z == 0 ? g_qhi : z == 1 ? g_khi : g_vhi;
                    __nv_bfloat16* dlo = z == 0 ? g_qlo : z == 1 ? g_klo : g_vlo;
                    const int bb = m >> 11, ss = m & (S - 1);
                    const int h = n >> 6, d0 = n & (DK - 1);
                    const size_t idx = ((size_t)(bb * H + h) * S + ss) * DK + d0;
                    __nv_bfloat162 hv = __float22bfloat162_rn(v);
                    float2 hf = __bfloat1622float2(hv);
                    __nv_bfloat162 lv = __float22bfloat162_rn(
                        make_float2(v.x - hf.x, v.y - hf.y));
                    *(__nv_bfloat162*)(dhi + idx) = hv;
                    *(__nv_bfloat162*)(dlo + idx) = lv;
                } else {
                    float2 bv = *(const float2*)(bias + n);
                    v.x += bv.x; v.y += bv.y;
                    *(float2*)(out_param + (size_t)m * D + n) = v;
                }
            }
        }
    }
}

// ---------------------------------------------------------------------------
// Tensor-core flash attention (R10/R11 configuration — best measured).
// 256 threads / 8 warps / 128 Q rows / 64-key tiles; exp2f with folded scale.
// ---------------------------------------------------------------------------
static constexpr int RST = 144;
static constexpr int KV_TERM = 64 * RST;        // 9216
static constexpr int KV_STG  = 4 * KV_TERM;     // 36864
static constexpr int ATTN_SMEM = 2 * KV_STG;    // 73728
static constexpr float SCALE_LOG2E = 0.125f * 1.4426950408889634f;

__global__ __launch_bounds__(256, 1) void flash_attn_tc()
{
    extern __shared__ char smc[];
    const uint32_t sb = smem_u32(smc);
    const int tid = threadIdx.x, lane = tid & 31, wid = tid >> 5;
    const int qb = (int)gridDim.x - 1 - (int)blockIdx.x;
    const int bh = blockIdx.y;
    const int ntiles = 2 * qb + 2;
    const size_t bho = (size_t)bh * S * DK;

    const __nv_bfloat16* qh_g = g_qhi + bho + (size_t)qb * 128 * DK;
    const __nv_bfloat16* ql_g = g_qlo + bho + (size_t)qb * 128 * DK;
    const __nv_bfloat16* kh_g = g_khi + bho;
    const __nv_bfloat16* kl_g = g_klo + bho;
    const __nv_bfloat16* vh_g = g_vhi + bho;
    const __nv_bfloat16* vl_g = g_vlo + bho;

    #pragma unroll
    for (int i = 0; i < 4; i++) {
        int u = tid + 256 * i, r = u >> 3, c = u & 7;
        cp16(sb + r * RST + c * 16, qh_g + r * DK + c * 8);
        cp16(sb + 2 * KV_TERM + r * RST + c * 16, ql_g + r * DK + c * 8);
    }
    cp_commit(); cp_wait<0>(); __syncthreads();

    const uint32_t a_lane = (uint32_t)((lane & 15) * RST + (lane >> 4) * 16);
    uint32_t qh[4][4], ql[4][4];
    #pragma unroll
    for (int kt = 0; kt < 4; kt++) {
        ldm_x4(qh[kt][0], qh[kt][1], qh[kt][2], qh[kt][3],
               sb + (uint32_t)(wid * 16) * RST + kt * 32 + a_lane);
        ldm_x4(ql[kt][0], ql[kt][1], ql[kt][2], ql[kt][3],
               sb + 2 * KV_TERM + (uint32_t)(wid * 16) * RST + kt * 32 + a_lane);
    }
    __syncthreads();

    const uint32_t b_lane = (uint32_t)(((((lane >> 4) & 1) * 8) + (lane & 7)) * RST
                                       + ((lane >> 3) & 1) * 16);
    const uint32_t v_lane = (uint32_t)(((((lane >> 3) & 1) * 8) + (lane & 7)) * RST
                                       + (lane >> 4) * 16);

    auto load_kv = [&](int nt, uint32_t dstb) {
        const int kb0 = nt * 64;
        #pragma unroll
        for (int i = 0; i < 2; i++) {
            int u = tid + 256 * i, r = u >> 3, c = u & 7;
            size_t g = (size_t)(kb0 + r) * DK + c * 8;
            uint32_t so = dstb + (uint32_t)(r * RST + c * 16);
            cp16(so + 0 * KV_TERM, kh_g + g);
            cp16(so + 1 * KV_TERM, kl_g + g);
            cp16(so + 2 * KV_TERM, vh_g + g);
            cp16(so + 3 * KV_TERM, vl_g + g);
        }
    };

    float o[8][4];
    #pragma unroll
    for (int j = 0; j < 8; j++)
        #pragma unroll
        for (int e = 0; e < 4; e++) o[j][e] = 0.f;
    float row_m[2] = {-1e30f, -1e30f}, row_l[2] = {0.f, 0.f};
    const int m0w = qb * 128 + wid * 16;

    load_kv(0, sb);
    cp_commit();

    for (int nt = 0; nt < ntiles; nt++) {
        if (nt + 1 < ntiles) {
            load_kv(nt + 1, sb + (uint32_t)((nt + 1) & 1) * KV_STG);
            cp_commit();
            cp_wait<1>();
        } else {
            cp_wait<0>();
        }
        __syncthreads();

        const int kbase = nt * 64;
        if (kbase <= m0w + 15) {
            const uint32_t stg = sb + (uint32_t)(nt & 1) * KV_STG;

            // ---- S = Q K^T ----
            float sc[8][4];
            #pragma unroll
            for (int j = 0; j < 8; j++)
                #pragma unroll
                for (int e = 0; e < 4; e++) sc[j][e] = 0.f;

            #pragma unroll
            for (int kt = 0; kt < 4; kt++) {
                #pragma unroll
                for (int nb = 0; nb < 4; nb++) {
                    uint32_t bk[4];
                    const uint32_t tb = (uint32_t)(nb * 16) * RST + kt * 32;
                    ldm_x4(bk[0], bk[1], bk[2], bk[3], stg + tb + b_lane);  // khi
                    #pragma unroll
                    for (int j2 = 0; j2 < 2; j2++) {
                        const int j = nb * 2 + j2;
                        mma_16816(sc[j][0], sc[j][1], sc[j][2], sc[j][3],
                                  qh[kt][0], qh[kt][1], qh[kt][2], qh[kt][3],
                                  bk[j2 * 2], bk[j2 * 2 + 1]);
                        mma_16816(sc[j][0], sc[j][1], sc[j][2], sc[j][3],
                                  ql[kt][0], ql[kt][1], ql[kt][2], ql[kt][3],
                                  bk[j2 * 2], bk[j2 * 2 + 1]);
                    }
                    ldm_x4(bk[0], bk[1], bk[2], bk[3],
                           stg + KV_TERM + tb + b_lane);                    // klo
                    #pragma unroll
                    for (int j2 = 0; j2 < 2; j2++) {
                        const int j = nb * 2 + j2;
                        mma_16816(sc[j][0], sc[j][1], sc[j][2], sc[j][3],
                                  qh[kt][0], qh[kt][1], qh[kt][2], qh[kt][3],
                                  bk[j2 * 2], bk[j2 * 2 + 1]);
                    }
                }
            }

            // scale (log2e folded) + causal mask
            const bool needm = (kbase + 63) > m0w;
            #pragma unroll
            for (int j = 0; j < 8; j++)
                #pragma unroll
                for (int e = 0; e < 4; e++) {
                    float x = sc[j][e] * SCALE_LOG2E;
                    if (needm) {
                        const int key = kbase + j * 8 + (lane & 3) * 2 + (e & 1);
                        const int row = m0w + (lane >> 2) + (e >> 1) * 8;
                        if (key > row) x = -1e30f;
                    }
                    sc[j][e] = x;
                }

            // ---- online softmax (base-2 domain) ----
            #pragma unroll
            for (int h2 = 0; h2 < 2; h2++) {
                float mx = -1e30f;
                #pragma unroll
                for (int j = 0; j < 8; j++)
                    mx = fmaxf(mx, fmaxf(sc[j][h2 * 2], sc[j][h2 * 2 + 1]));
                mx = fmaxf(mx, __shfl_xor_sync(0xffffffffu, mx, 1));
                mx = fmaxf(mx, __shfl_xor_sync(0xffffffffu, mx, 2));
                const float mn = fmaxf(row_m[h2], mx);
                const float corr = exp2f(row_m[h2] - mn);
                float sum = 0.f;
                #pragma unroll
                for (int j = 0; j < 8; j++) {
                    float p0 = exp2f(sc[j][h2 * 2] - mn);
                    float p1 = exp2f(sc[j][h2 * 2 + 1] - mn);
                    sc[j][h2 * 2] = p0; sc[j][h2 * 2 + 1] = p1;
                    sum += p0 + p1;
                }
                sum += __shfl_xor_sync(0xffffffffu, sum, 1);
                sum += __shfl_xor_sync(0xffffffffu, sum, 2);
                row_l[h2] = row_l[h2] * corr + sum;
                row_m[h2] = mn;
                #pragma unroll
                for (int j = 0; j < 8; j++) {
                    o[j][h2 * 2] *= corr;
                    o[j][h2 * 2 + 1] *= corr;
                }
            }

            // ---- pack P into bf16 hi/lo A-fragments ----
            uint32_t pHi[8][2], pLo[8][2];
            #pragma unroll
            for (int j = 0; j < 8; j++)
                #pragma unroll
                for (int pr = 0; pr < 2; pr++) {
                    float p0 = sc[j][pr * 2], p1 = sc[j][pr * 2 + 1];
                    __nv_bfloat162 hv = __float22bfloat162_rn(make_float2(p0, p1));
                    float2 hf = __bfloat1622float2(hv);
                    __nv_bfloat162 lv = __float22bfloat162_rn(
                        make_float2(p0 - hf.x, p1 - hf.y));
                    pHi[j][pr] = *(uint32_t*)&hv;
                    pLo[j][pr] = *(uint32_t*)&lv;
                }

            // ---- O += P V ----
            #pragma unroll
            for (int kt = 0; kt < 4; kt++) {
                const uint32_t ah0 = pHi[2 * kt][0], ah1 = pHi[2 * kt][1];
                const uint32_t ah2 = pHi[2 * kt + 1][0], ah3 = pHi[2 * kt + 1][1];
                const uint32_t al0 = pLo[2 * kt][0], al1 = pLo[2 * kt][1];
                const uint32_t al2 = pLo[2 * kt + 1][0], al3 = pLo[2 * kt + 1][1];
                #pragma unroll
                for (int nb = 0; nb < 4; nb++) {
                    uint32_t bv[4];
                    const uint32_t tb = (uint32_t)(kt * 16) * RST + nb * 32;
                    ldm_x4_t(bv[0], bv[1], bv[2], bv[3],
                             stg + 2 * KV_TERM + tb + v_lane);               // vhi
                    #pragma unroll
                    for (int j2 = 0; j2 < 2; j2++) {
                        const int j = nb * 2 + j2;
                        mma_16816(o[j][0], o[j][1], o[j][2], o[j][3],
                                  ah0, ah1, ah2, ah3, bv[j2 * 2], bv[j2 * 2 + 1]);
                        mma_16816(o[j][0], o[j][1], o[j][2], o[j][3],
                                  al0, al1, al2, al3, bv[j2 * 2], bv[j2 * 2 + 1]);
                    }
                    ldm_x4_t(bv[0], bv[1], bv[2], bv[3],
                             stg + 3 * KV_TERM + tb + v_lane);               // vlo
                    #pragma unroll
                    for (int j2 = 0; j2 < 2; j2++) {
                        const int j = nb * 2 + j2;
                        mma_16816(o[j][0], o[j][1], o[j][2], o[j][3],
                                  ah0, ah1, ah2, ah3, bv[j2 * 2], bv[j2 * 2 + 1]);
                    }
                }
            }
        }
        __syncthreads();
    }

    // ---- epilogue: normalize + bf16 hi/lo split into out-proj A ----
    const int b = bh >> 4, head = bh & (H - 1);
    #pragma unroll
    for (int h2 = 0; h2 < 2; h2++) {
        const float inv = 1.0f / row_l[h2];
        const int row = m0w + (lane >> 2) + h2 * 8;
        #pragma unroll
        for (int j = 0; j < 8; j++) {
            const int col = head * DK + j * 8 + (lane & 3) * 2;
            const size_t idx = (size_t)(b * S + row) * D + col;
            float2 v = make_float2(o[j][h2 * 2] * inv, o[j][h2 * 2 + 1] * inv);
            __nv_bfloat162 hv = __float22bfloat162_rn(v);
            float2 hf = __bfloat1622float2(hv);
            __nv_bfloat162 lv = __float22bfloat162_rn(
                make_float2(v.x - hf.x, v.y - hf.y));
            *(__nv_bfloat162*)(g_Ahi + idx) = hv;
            *(__nv_bfloat162*)(g_Alo + idx) = lv;
        }
    }
}

// ---------------------------------------------------------------------------
extern "C" void kernel_launch(void* const* d_in, const int* in_sizes, int n_in,
                              void* d_out, int out_size)
{
    const float* Q  = (const float*)d_in[0];
    const float* K  = (const float*)d_in[1];
    const float* V  = (const float*)d_in[2];
    const float* Wq = (const float*)d_in[3];
    const float* Wk = (const float*)d_in[4];
    const float* Wv = (const float*)d_in[5];
    const float* Wo = (const float*)d_in[6];
    const float* bo = (const float*)d_in[7];
    float* out = (float*)d_out;

    (void)in_sizes; (void)n_in; (void)out_size;

    cudaFuncSetAttribute(tc_gemm_kernel<0>,
                         cudaFuncAttributeMaxDynamicSharedMemorySize, GEMM_SMEM0);
    cudaFuncSetAttribute(tc_gemm_kernel<1>,
                         cudaFuncAttributeMaxDynamicSharedMemorySize, GEMM_SMEM1);
    cudaFuncSetAttribute(flash_attn_tc,
                         cudaFuncAttributeMaxDynamicSharedMemorySize, ATTN_SMEM);

    // weight transpose + split (small)
    convert_w_kernel<<<dim3(D / 32, D / 32, 4), dim3(32, 8)>>>(Wq, Wk, Wv, Wo);

    // Q/K/V projections: fp32 A staged + split in-kernel
    tc_gemm_kernel<0><<<dim3(D / GBN, M / GBM, 3), 256, GEMM_SMEM0>>>(
        Q, K, V, nullptr, nullptr);

    // Tensor-core flash attention (writes out-proj A operand directly)
    flash_attn_tc<<<dim3(S / 128, B * H), 256, ATTN_SMEM>>>();

    // Output projection (+bias)
    tc_gemm_kernel<1><<<dim3(D / GBN, M / GBM, 1), 256, GEMM_SMEM1>>>(
        nullptr, nullptr, nullptr, out, bo);
}

// round 13
// speedup vs baseline: 1.0522x; 1.0522x over previous
#include <cuda_runtime.h>
#include <cuda_bf16.h>
#include <cstdint>

// Problem constants
static constexpr int B  = 2;
static constexpr int S  = 2048;
static constexpr int D  = 1024;
static constexpr int H  = 16;
static constexpr int DK = 64;
static constexpr int M  = B * S;   // 4096

// ---------------------------------------------------------------------------
// Device scratch
// ---------------------------------------------------------------------------
__device__ __nv_bfloat16 g_qhi[(size_t)B * H * S * DK];
__device__ __nv_bfloat16 g_qlo[(size_t)B * H * S * DK];
__device__ __nv_bfloat16 g_khi[(size_t)B * H * S * DK];
__device__ __nv_bfloat16 g_klo[(size_t)B * H * S * DK];
__device__ __nv_bfloat16 g_vhi[(size_t)B * H * S * DK];
__device__ __nv_bfloat16 g_vlo[(size_t)B * H * S * DK];

__device__ __nv_bfloat16 g_Ahi[3 * (size_t)M * D];
__device__ __nv_bfloat16 g_Alo[3 * (size_t)M * D];
__device__ __nv_bfloat16 g_Bhi[4 * (size_t)D * D];
__device__ __nv_bfloat16 g_Blo[4 * (size_t)D * D];

// ---------------------------------------------------------------------------
// PTX helpers
// ---------------------------------------------------------------------------
__device__ __forceinline__ uint32_t smem_u32(const void* p) {
    uint32_t a;
    asm("{ .reg .u64 t; cvta.to.shared.u64 t, %1; cvt.u32.u64 %0, t; }"
        : "=r"(a) : "l"(p));
    return a;
}
__device__ __forceinline__ void cp16(uint32_t saddr, const void* g) {
    asm volatile("cp.async.cg.shared.global [%0], [%1], 16;"
                 :: "r"(saddr), "l"(g) : "memory");
}
__device__ __forceinline__ void cp_commit() {
    asm volatile("cp.async.commit_group;" ::: "memory");
}
template <int N>
__device__ __forceinline__ void cp_wait() {
    asm volatile("cp.async.wait_group %0;" :: "n"(N) : "memory");
}
__device__ __forceinline__ void ldm_x4(uint32_t& r0, uint32_t& r1,
                                       uint32_t& r2, uint32_t& r3, uint32_t a) {
    asm volatile("ldmatrix.sync.aligned.m8n8.x4.shared.b16 {%0,%1,%2,%3}, [%4];"
                 : "=r"(r0), "=r"(r1), "=r"(r2), "=r"(r3) : "r"(a));
}
__device__ __forceinline__ void ldm_x4_t(uint32_t& r0, uint32_t& r1,
                                         uint32_t& r2, uint32_t& r3, uint32_t a) {
    asm volatile("ldmatrix.sync.aligned.m8n8.x4.trans.shared.b16 {%0,%1,%2,%3}, [%4];"
                 : "=r"(r0), "=r"(r1), "=r"(r2), "=r"(r3) : "r"(a));
}
__device__ __forceinline__ void mma_16816(float& c0, float& c1, float& c2, float& c3,
                                          uint32_t a0, uint32_t a1, uint32_t a2,
                                          uint32_t a3, uint32_t b0, uint32_t b1) {
    asm volatile(
        "mma.sync.aligned.m16n8k16.row.col.f32.bf16.bf16.f32 "
        "{%0,%1,%2,%3}, {%4,%5,%6,%7}, {%8,%9}, {%0,%1,%2,%3};"
        : "+f"(c0), "+f"(c1), "+f"(c2), "+f"(c3)
        : "r"(a0), "r"(a1), "r"(a2), "r"(a3), "r"(b0), "r"(b1));
}

// ---------------------------------------------------------------------------
// fp32 -> bf16 hi/lo converts — streaming-optimized
// ---------------------------------------------------------------------------
// 16 floats per thread (4 x float4, 4KB stride) for MLP>=4
__global__ __launch_bounds__(256) void convert_a_kernel(
    const float* __restrict__ p0, const float* __restrict__ p1,
    const float* __restrict__ p2)
{
    const int z = blockIdx.z;
    const float* src = (z == 0 ? p0 : z == 1 ? p1 : p2);
    const size_t base = (size_t)z * ((size_t)M * D);
    const size_t i0 = (size_t)blockIdx.x * (256 * 16) + (size_t)threadIdx.x * 4;

    float4 v[4];
    #pragma unroll
    for (int r = 0; r < 4; r++)
        v[r] = *(const float4*)(src + i0 + (size_t)r * (256 * 4));

    #pragma unroll
    for (int r = 0; r < 4; r++) {
        const size_t i = i0 + (size_t)r * (256 * 4);
        float x[4] = {v[r].x, v[r].y, v[r].z, v[r].w};
        __nv_bfloat16 hi[4], lo[4];
        #pragma unroll
        for (int j = 0; j < 4; j++) {
            hi[j] = __float2bfloat16(x[j]);
            lo[j] = __float2bfloat16(x[j] - __bfloat162float(hi[j]));
        }
        *(uint2*)&g_Ahi[base + i] = *(uint2*)hi;
        *(uint2*)&g_Alo[base + i] = *(uint2*)lo;
    }
}

// Transpose + split W: Wt[n][k] = W[k][n].  64k x 32n tiles, bf16x2 stores.
__global__ void convert_w_kernel(const float* __restrict__ w0,
                                 const float* __restrict__ w1,
                                 const float* __restrict__ w2,
                                 const float* __restrict__ w3)
{
    __shared__ float t[64][33];
    const int z = blockIdx.z;
    const float* W = z == 0 ? w0 : z == 1 ? w1 : z == 2 ? w2 : w3;
    const size_t base = (size_t)z * D * D;
    const int n0 = blockIdx.x * 32, k0 = blockIdx.y * 64;
    const int tx = threadIdx.x, ty = threadIdx.y;

    for (int i = ty; i < 64; i += 8)
        t[i][tx] = W[(size_t)(k0 + i) * D + n0 + tx];
    __syncthreads();
    for (int i = ty; i < 32; i += 8) {
        float x0 = t[2 * tx][i];          // W[k0+2tx][n0+i]
        float x1 = t[2 * tx + 1][i];
        __nv_bfloat162 h2 = __float22bfloat162_rn(make_float2(x0, x1));
        float2 hf = __bfloat1622float2(h2);
        __nv_bfloat162 l2 = __float22bfloat162_rn(
            make_float2(x0 - hf.x, x1 - hf.y));
        const size_t o = base + (size_t)(n0 + i) * D + k0 + 2 * tx;
        *(__nv_bfloat162*)&g_Bhi[o] = h2;
        *(__nv_bfloat162*)&g_Blo[o] = l2;
    }
}

// ---------------------------------------------------------------------------
// bf16 mma.sync GEMM (R6/R11 configuration — best measured).
// CTA 128x128, BK=64, 8 warps (64x32 tiles), 2-stage 144KB smem.
// ---------------------------------------------------------------------------
static constexpr int GBM = 128, GBN = 128, GBK = 64;
static constexpr int NC = D / GBK;                 // 16 chunks
static constexpr int RSTRIDE = 144;                // 128B data + 16B pad
static constexpr int TILE_B  = 128 * RSTRIDE;      // 18432
static constexpr int OA_HI = 0, OA_LO = TILE_B, OB_HI = 2 * TILE_B, OB_LO = 3 * TILE_B;
static constexpr int STG = 4 * TILE_B;             // 73728 per stage
static constexpr int GEMM_SMEM = 2 * STG;          // 147456

__device__ __forceinline__ void load_tile(const __nv_bfloat16* __restrict__ src,
                                          int row0, int k0, uint32_t sdst, int tid)
{
    #pragma unroll
    for (int i = 0; i < 4; i++) {
        int unit = tid + 256 * i;
        int r = unit >> 3, c = unit & 7;
        cp16(sdst + r * RSTRIDE + c * 16,
             src + (size_t)(row0 + r) * D + k0 + c * 8);
    }
}

template <int MODE>
__global__ __launch_bounds__(256, 1) void tc_gemm_kernel(
    float* __restrict__ out_param, const float* __restrict__ bias)
{
    extern __shared__ char smc[];
    const uint32_t sb = smem_u32(smc);
    const int tid = threadIdx.x;
    const int lane = tid & 31, wid = tid >> 5;
    const int z = blockIdx.z;
    const int bm = blockIdx.y * GBM;
    const int bn = blockIdx.x * GBN;

    const __nv_bfloat16* Ahi = g_Ahi + (MODE == 0 ? (size_t)z * M * D : 0);
    const __nv_bfloat16* Alo = g_Alo + (MODE == 0 ? (size_t)z * M * D : 0);
    const __nv_bfloat16* Bhi = g_Bhi + (MODE == 0 ? (size_t)z * D * D : (size_t)3 * D * D);
    const __nv_bfloat16* Blo = g_Blo + (MODE == 0 ? (size_t)z * D * D : (size_t)3 * D * D);

    const int m_warp = (wid & 1) * 64;
    const int n_warp = (wid >> 1) * 32;

    const uint32_t a_lane = (uint32_t)((lane & 15) * RSTRIDE + ((lane >> 4) & 1) * 16);
    const uint32_t b_lane = (uint32_t)((((lane >> 4) & 1) * 8 + (lane & 7)) * RSTRIDE
                                       + ((lane >> 3) & 1) * 16);

    float acc[4][4][4];
    #pragma unroll
    for (int i = 0; i < 4; i++)
        #pragma unroll
        for (int j = 0; j < 4; j++)
            #pragma unroll
            for (int e = 0; e < 4; e++) acc[i][j][e] = 0.f;

    load_tile(Ahi, bm, 0, sb + OA_HI, tid);
    load_tile(Alo, bm, 0, sb + OA_LO, tid);
    load_tile(Bhi, bn, 0, sb + OB_HI, tid);
    load_tile(Blo, bn, 0, sb + OB_LO, tid);
    cp_commit();

    for (int c = 0; c < NC; c++) {
        const int s = c & 1;
        if (c + 1 < NC) {
            const uint32_t nb = sb + (s ^ 1) * STG;
            const int k0 = (c + 1) * GBK;
            load_tile(Ahi, bm, k0, nb + OA_HI, tid);
            load_tile(Alo, bm, k0, nb + OA_LO, tid);
            load_tile(Bhi, bn, k0, nb + OB_HI, tid);
            load_tile(Blo, bn, k0, nb + OB_LO, tid);
            cp_commit();
            cp_wait<1>();
        } else {
            cp_wait<0>();
        }
        __syncthreads();

        const uint32_t stg = sb + s * STG;
        #pragma unroll
        for (int t = 0; t < 4; t++) {
            uint32_t ah[4][4], al[4][4];
            #pragma unroll
            for (int i = 0; i < 4; i++) {
                const uint32_t ro = (uint32_t)((m_warp + i * 16) * RSTRIDE + t * 32) + a_lane;
                ldm_x4(ah[i][0], ah[i][1], ah[i][2], ah[i][3], stg + OA_HI + ro);
                ldm_x4(al[i][0], al[i][1], al[i][2], al[i][3], stg + OA_LO + ro);
            }
            uint32_t bh[8], bl[8];
            #pragma unroll
            for (int p = 0; p < 2; p++) {
                const uint32_t ro = (uint32_t)((n_warp + p * 16) * RSTRIDE + t * 32) + b_lane;
                ldm_x4(bh[p * 4 + 0], bh[p * 4 + 1], bh[p * 4 + 2], bh[p * 4 + 3],
                       stg + OB_HI + ro);
                ldm_x4(bl[p * 4 + 0], bl[p * 4 + 1], bl[p * 4 + 2], bl[p * 4 + 3],
                       stg + OB_LO + ro);
            }
            #pragma unroll
            for (int i = 0; i < 4; i++)
                #pragma unroll
                for (int j = 0; j < 4; j++) {
                    const int bi = (j >> 1) * 4 + (j & 1) * 2;
                    mma_16816(acc[i][j][0], acc[i][j][1], acc[i][j][2], acc[i][j][3],
                              ah[i][0], ah[i][1], ah[i][2], ah[i][3],
                              bh[bi], bh[bi + 1]);
                    mma_16816(acc[i][j][0], acc[i][j][1], acc[i][j][2], acc[i][j][3],
                              ah[i][0], ah[i][1], ah[i][2], ah[i][3],
                              bl[bi], bl[bi + 1]);
                    mma_16816(acc[i][j][0], acc[i][j][1], acc[i][j][2], acc[i][j][3],
                              al[i][0], al[i][1], al[i][2], al[i][3],
                              bh[bi], bh[bi + 1]);
                }
        }
        __syncthreads();
    }

    // Epilogue
    const int g = lane >> 2, tq = lane & 3;
    #pragma unroll
    for (int i = 0; i < 4; i++) {
        #pragma unroll
        for (int j = 0; j < 4; j++) {
            const int n = bn + n_warp + j * 8 + tq * 2;
            #pragma unroll
            for (int half = 0; half < 2; half++) {
                const int m = bm + m_warp + i * 16 + g + half * 8;
                float2 v = make_float2(acc[i][j][half * 2], acc[i][j][half * 2 + 1]);
                if (MODE == 0) {
                    __nv_bfloat16* dhi = z == 0 ? g_qhi : z == 1 ? g_khi : g_vhi;
                    __nv_bfloat16* dlo = z == 0 ? g_qlo : z == 1 ? g_klo : g_vlo;
                    const int bb = m >> 11, ss = m & (S - 1);
                    const int h = n >> 6, d0 = n & (DK - 1);
                    const size_t idx = ((size_t)(bb * H + h) * S + ss) * DK + d0;
                    __nv_bfloat162 hv = __float22bfloat162_rn(v);
                    float2 hf = __bfloat1622float2(hv);
                    __nv_bfloat162 lv = __float22bfloat162_rn(
                        make_float2(v.x - hf.x, v.y - hf.y));
                    *(__nv_bfloat162*)(dhi + idx) = hv;
                    *(__nv_bfloat162*)(dlo + idx) = lv;
                } else {
                    float2 bv = *(const float2*)(bias + n);
                    v.x += bv.x; v.y += bv.y;
                    *(float2*)(out_param + (size_t)m * D + n) = v;
                }
            }
        }
    }
}

// ---------------------------------------------------------------------------
// Tensor-core flash attention (R10/R11 configuration — best measured).
// 256 threads / 8 warps / 128 Q rows / 64-key tiles; exp2f with folded scale.
// ---------------------------------------------------------------------------
static constexpr int RST = 144;
static constexpr int KV_TERM = 64 * RST;        // 9216
static constexpr int KV_STG  = 4 * KV_TERM;     // 36864
static constexpr int ATTN_SMEM = 2 * KV_STG;    // 73728
static constexpr float SCALE_LOG2E = 0.125f * 1.4426950408889634f;

__global__ __launch_bounds__(256, 1) void flash_attn_tc()
{
    extern __shared__ char smc[];
    const uint32_t sb = smem_u32(smc);
    const int tid = threadIdx.x, lane = tid & 31, wid = tid >> 5;
    const int qb = (int)gridDim.x - 1 - (int)blockIdx.x;
    const int bh = blockIdx.y;
    const int ntiles = 2 * qb + 2;
    const size_t bho = (size_t)bh * S * DK;

    const __nv_bfloat16* qh_g = g_qhi + bho + (size_t)qb * 128 * DK;
    const __nv_bfloat16* ql_g = g_qlo + bho + (size_t)qb * 128 * DK;
    const __nv_bfloat16* kh_g = g_khi + bho;
    const __nv_bfloat16* kl_g = g_klo + bho;
    const __nv_bfloat16* vh_g = g_vhi + bho;
    const __nv_bfloat16* vl_g = g_vlo + bho;

    #pragma unroll
    for (int i = 0; i < 4; i++) {
        int u = tid + 256 * i, r = u >> 3, c = u & 7;
        cp16(sb + r * RST + c * 16, qh_g + r * DK + c * 8);
        cp16(sb + 2 * KV_TERM + r * RST + c * 16, ql_g + r * DK + c * 8);
    }
    cp_commit(); cp_wait<0>(); __syncthreads();

    const uint32_t a_lane = (uint32_t)((lane & 15) * RST + (lane >> 4) * 16);
    uint32_t qh[4][4], ql[4][4];
    #pragma unroll
    for (int kt = 0; kt < 4; kt++) {
        ldm_x4(qh[kt][0], qh[kt][1], qh[kt][2], qh[kt][3],
               sb + (uint32_t)(wid * 16) * RST + kt * 32 + a_lane);
        ldm_x4(ql[kt][0], ql[kt][1], ql[kt][2], ql[kt][3],
               sb + 2 * KV_TERM + (uint32_t)(wid * 16) * RST + kt * 32 + a_lane);
    }
    __syncthreads();

    const uint32_t b_lane = (uint32_t)(((((lane >> 4) & 1) * 8) + (lane & 7)) * RST
                                       + ((lane >> 3) & 1) * 16);
    const uint32_t v_lane = (uint32_t)(((((lane >> 3) & 1) * 8) + (lane & 7)) * RST
                                       + (lane >> 4) * 16);

    auto load_kv = [&](int nt, uint32_t dstb) {
        const int kb0 = nt * 64;
        #pragma unroll
        for (int i = 0; i < 2; i++) {
            int u = tid + 256 * i, r = u >> 3, c = u & 7;
            size_t g = (size_t)(kb0 + r) * DK + c * 8;
            uint32_t so = dstb + (uint32_t)(r * RST + c * 16);
            cp16(so + 0 * KV_TERM, kh_g + g);
            cp16(so + 1 * KV_TERM, kl_g + g);
            cp16(so + 2 * KV_TERM, vh_g + g);
            cp16(so + 3 * KV_TERM, vl_g + g);
        }
    };

    float o[8][4];
    #pragma unroll
    for (int j = 0; j < 8; j++)
        #pragma unroll
        for (int e = 0; e < 4; e++) o[j][e] = 0.f;
    float row_m[2] = {-1e30f, -1e30f}, row_l[2] = {0.f, 0.f};
    const int m0w = qb * 128 + wid * 16;

    load_kv(0, sb);
    cp_commit();

    for (int nt = 0; nt < ntiles; nt++) {
        if (nt + 1 < ntiles) {
            load_kv(nt + 1, sb + (uint32_t)((nt + 1) & 1) * KV_STG);
            cp_commit();
            cp_wait<1>();
        } else {
            cp_wait<0>();
        }
        __syncthreads();

        const int kbase = nt * 64;
        if (kbase <= m0w + 15) {
            const uint32_t stg = sb + (uint32_t)(nt & 1) * KV_STG;

            // ---- S = Q K^T ----
            float sc[8][4];
            #pragma unroll
            for (int j = 0; j < 8; j++)
                #pragma unroll
                for (int e = 0; e < 4; e++) sc[j][e] = 0.f;

            #pragma unroll
            for (int kt = 0; kt < 4; kt++) {
                #pragma unroll
                for (int nb = 0; nb < 4; nb++) {
                    uint32_t bk[4];
                    const uint32_t tb = (uint32_t)(nb * 16) * RST + kt * 32;
                    ldm_x4(bk[0], bk[1], bk[2], bk[3], stg + tb + b_lane);  // khi
                    #pragma unroll
                    for (int j2 = 0; j2 < 2; j2++) {
                        const int j = nb * 2 + j2;
                        mma_16816(sc[j][0], sc[j][1], sc[j][2], sc[j][3],
                                  qh[kt][0], qh[kt][1], qh[kt][2], qh[kt][3],
                                  bk[j2 * 2], bk[j2 * 2 + 1]);
                        mma_16816(sc[j][0], sc[j][1], sc[j][2], sc[j][3],
                                  ql[kt][0], ql[kt][1], ql[kt][2], ql[kt][3],
                                  bk[j2 * 2], bk[j2 * 2 + 1]);
                    }
                    ldm_x4(bk[0], bk[1], bk[2], bk[3],
                           stg + KV_TERM + tb + b_lane);                    // klo
                    #pragma unroll
                    for (int j2 = 0; j2 < 2; j2++) {
                        const int j = nb * 2 + j2;
                        mma_16816(sc[j][0], sc[j][1], sc[j][2], sc[j][3],
                                  qh[kt][0], qh[kt][1], qh[kt][2], qh[kt][3],
                                  bk[j2 * 2], bk[j2 * 2 + 1]);
                    }
                }
            }

            // scale (log2e folded) + causal mask
            const bool needm = (kbase + 63) > m0w;
            #pragma unroll
            for (int j = 0; j < 8; j++)
                #pragma unroll
                for (int e = 0; e < 4; e++) {
                    float x = sc[j][e] * SCALE_LOG2E;
                    if (needm) {
                        const int key = kbase + j * 8 + (lane & 3) * 2 + (e & 1);
                        const int row = m0w + (lane >> 2) + (e >> 1) * 8;
                        if (key > row) x = -1e30f;
                    }
                    sc[j][e] = x;
                }

            // ---- online softmax (base-2 domain) ----
            #pragma unroll
            for (int h2 = 0; h2 < 2; h2++) {
                float mx = -1e30f;
                #pragma unroll
                for (int j = 0; j < 8; j++)
                    mx = fmaxf(mx, fmaxf(sc[j][h2 * 2], sc[j][h2 * 2 + 1]));
                mx = fmaxf(mx, __shfl_xor_sync(0xffffffffu, mx, 1));
                mx = fmaxf(mx, __shfl_xor_sync(0xffffffffu, mx, 2));
                const float mn = fmaxf(row_m[h2], mx);
                const float corr = exp2f(row_m[h2] - mn);
                float sum = 0.f;
                #pragma unroll
                for (int j = 0; j < 8; j++) {
                    float p0 = exp2f(sc[j][h2 * 2] - mn);
                    float p1 = exp2f(sc[j][h2 * 2 + 1] - mn);
                    sc[j][h2 * 2] = p0; sc[j][h2 * 2 + 1] = p1;
                    sum += p0 + p1;
                }
                sum += __shfl_xor_sync(0xffffffffu, sum, 1);
                sum += __shfl_xor_sync(0xffffffffu, sum, 2);
                row_l[h2] = row_l[h2] * corr + sum;
                row_m[h2] = mn;
                #pragma unroll
                for (int j = 0; j < 8; j++) {
                    o[j][h2 * 2] *= corr;
                    o[j][h2 * 2 + 1] *= corr;
                }
            }

            // ---- pack P into bf16 hi/lo A-fragments ----
            uint32_t pHi[8][2], pLo[8][2];
            #pragma unroll
            for (int j = 0; j < 8; j++)
                #pragma unroll
                for (int pr = 0; pr < 2; pr++) {
                    float p0 = sc[j][pr * 2], p1 = sc[j][pr * 2 + 1];
                    __nv_bfloat162 hv = __float22bfloat162_rn(make_float2(p0, p1));
                    float2 hf = __bfloat1622float2(hv);
                    __nv_bfloat162 lv = __float22bfloat162_rn(
                        make_float2(p0 - hf.x, p1 - hf.y));
                    pHi[j][pr] = *(uint32_t*)&hv;
                    pLo[j][pr] = *(uint32_t*)&lv;
                }

            // ---- O += P V ----
            #pragma unroll
            for (int kt = 0; kt < 4; kt++) {
                const uint32_t ah0 = pHi[2 * kt][0], ah1 = pHi[2 * kt][1];
                const uint32_t ah2 = pHi[2 * kt + 1][0], ah3 = pHi[2 * kt + 1][1];
                const uint32_t al0 = pLo[2 * kt][0], al1 = pLo[2 * kt][1];
                const uint32_t al2 = pLo[2 * kt + 1][0], al3 = pLo[2 * kt + 1][1];
                #pragma unroll
                for (int nb = 0; nb < 4; nb++) {
                    uint32_t bv[4];
                    const uint32_t tb = (uint32_t)(kt * 16) * RST + nb * 32;
                    ldm_x4_t(bv[0], bv[1], bv[2], bv[3],
                             stg + 2 * KV_TERM + tb + v_lane);               // vhi
                    #pragma unroll
                    for (int j2 = 0; j2 < 2; j2++) {
                        const int j = nb * 2 + j2;
                        mma_16816(o[j][0], o[j][1], o[j][2], o[j][3],
                                  ah0, ah1, ah2, ah3, bv[j2 * 2], bv[j2 * 2 + 1]);
                        mma_16816(o[j][0], o[j][1], o[j][2], o[j][3],
                                  al0, al1, al2, al3, bv[j2 * 2], bv[j2 * 2 + 1]);
                    }
                    ldm_x4_t(bv[0], bv[1], bv[2], bv[3],
                             stg + 3 * KV_TERM + tb + v_lane);               // vlo
                    #pragma unroll
                    for (int j2 = 0; j2 < 2; j2++) {
                        const int j = nb * 2 + j2;
                        mma_16816(o[j][0], o[j][1], o[j][2], o[j][3],
                                  ah0, ah1, ah2, ah3, bv[j2 * 2], bv[j2 * 2 + 1]);
                    }
                }
            }
        }
        __syncthreads();
    }

    // ---- epilogue: normalize + bf16 hi/lo split into out-proj A ----
    const int b = bh >> 4, head = bh & (H - 1);
    #pragma unroll
    for (int h2 = 0; h2 < 2; h2++) {
        const float inv = 1.0f / row_l[h2];
        const int row = m0w + (lane >> 2) + h2 * 8;
        #pragma unroll
        for (int j = 0; j < 8; j++) {
            const int col = head * DK + j * 8 + (lane & 3) * 2;
            const size_t idx = (size_t)(b * S + row) * D + col;
            float2 v = make_float2(o[j][h2 * 2] * inv, o[j][h2 * 2 + 1] * inv);
            __nv_bfloat162 hv = __float22bfloat162_rn(v);
            float2 hf = __bfloat1622float2(hv);
            __nv_bfloat162 lv = __float22bfloat162_rn(
                make_float2(v.x - hf.x, v.y - hf.y));
            *(__nv_bfloat162*)(g_Ahi + idx) = hv;
            *(__nv_bfloat162*)(g_Alo + idx) = lv;
        }
    }
}

// ---------------------------------------------------------------------------
extern "C" void kernel_launch(void* const* d_in, const int* in_sizes, int n_in,
                              void* d_out, int out_size)
{
    const float* Q  = (const float*)d_in[0];
    const float* K  = (const float*)d_in[1];
    const float* V  = (const float*)d_in[2];
    const float* Wq = (const float*)d_in[3];
    const float* Wk = (const float*)d_in[4];
    const float* Wv = (const float*)d_in[5];
    const float* Wo = (const float*)d_in[6];
    const float* bo = (const float*)d_in[7];
    float* out = (float*)d_out;

    (void)in_sizes; (void)n_in; (void)out_size;

    cudaFuncSetAttribute(tc_gemm_kernel<0>,
                         cudaFuncAttributeMaxDynamicSharedMemorySize, GEMM_SMEM);
    cudaFuncSetAttribute(tc_gemm_kernel<1>,
                         cudaFuncAttributeMaxDynamicSharedMemorySize, GEMM_SMEM);
    cudaFuncSetAttribute(flash_attn_tc,
                         cudaFuncAttributeMaxDynamicSharedMemorySize, ATTN_SMEM);

    convert_a_kernel<<<dim3(M * D / (256 * 16), 1, 3), 256>>>(Q, K, V);
    convert_w_kernel<<<dim3(D / 32, D / 64, 4), dim3(32, 8)>>>(Wq, Wk, Wv, Wo);

    tc_gemm_kernel<0><<<dim3(D / GBN, M / GBM, 3), 256, GEMM_SMEM>>>(nullptr, nullptr);

    flash_attn_tc<<<dim3(S / 128, B * H), 256, ATTN_SMEM>>>();

    tc_gemm_kernel<1><<<dim3(D / GBN, M / GBM, 1), 256, GEMM_SMEM>>>(out, bo);
}

// round 14
// speedup vs baseline: 1.0541x; 1.0018x over previous
#include <cuda_runtime.h>
#include <cuda_bf16.h>
#include <cstdint>

// Problem constants
static constexpr int B  = 2;
static constexpr int S  = 2048;
static constexpr int D  = 1024;
static constexpr int H  = 16;
static constexpr int DK = 64;
static constexpr int M  = B * S;   // 4096

// ---------------------------------------------------------------------------
// Device scratch
// ---------------------------------------------------------------------------
__device__ __nv_bfloat16 g_qhi[(size_t)B * H * S * DK];
__device__ __nv_bfloat16 g_qlo[(size_t)B * H * S * DK];
__device__ __nv_bfloat16 g_khi[(size_t)B * H * S * DK];
__device__ __nv_bfloat16 g_klo[(size_t)B * H * S * DK];
__device__ __nv_bfloat16 g_vhi[(size_t)B * H * S * DK];
__device__ __nv_bfloat16 g_vlo[(size_t)B * H * S * DK];

__device__ __nv_bfloat16 g_Ahi[3 * (size_t)M * D];
__device__ __nv_bfloat16 g_Alo[3 * (size_t)M * D];
__device__ __nv_bfloat16 g_Bhi[4 * (size_t)D * D];
__device__ __nv_bfloat16 g_Blo[4 * (size_t)D * D];

// ---------------------------------------------------------------------------
// PTX helpers
// ---------------------------------------------------------------------------
__device__ __forceinline__ uint32_t smem_u32(const void* p) {
    uint32_t a;
    asm("{ .reg .u64 t; cvta.to.shared.u64 t, %1; cvt.u32.u64 %0, t; }"
        : "=r"(a) : "l"(p));
    return a;
}
__device__ __forceinline__ void cp16(uint32_t saddr, const void* g) {
    asm volatile("cp.async.cg.shared.global [%0], [%1], 16;"
                 :: "r"(saddr), "l"(g) : "memory");
}
__device__ __forceinline__ void cp_commit() {
    asm volatile("cp.async.commit_group;" ::: "memory");
}
template <int N>
__device__ __forceinline__ void cp_wait() {
    asm volatile("cp.async.wait_group %0;" :: "n"(N) : "memory");
}
__device__ __forceinline__ void ldm_x4(uint32_t& r0, uint32_t& r1,
                                       uint32_t& r2, uint32_t& r3, uint32_t a) {
    asm volatile("ldmatrix.sync.aligned.m8n8.x4.shared.b16 {%0,%1,%2,%3}, [%4];"
                 : "=r"(r0), "=r"(r1), "=r"(r2), "=r"(r3) : "r"(a));
}
__device__ __forceinline__ void ldm_x4_t(uint32_t& r0, uint32_t& r1,
                                         uint32_t& r2, uint32_t& r3, uint32_t a) {
    asm volatile("ldmatrix.sync.aligned.m8n8.x4.trans.shared.b16 {%0,%1,%2,%3}, [%4];"
                 : "=r"(r0), "=r"(r1), "=r"(r2), "=r"(r3) : "r"(a));
}
__device__ __forceinline__ void mma_16816(float& c0, float& c1, float& c2, float& c3,
                                          uint32_t a0, uint32_t a1, uint32_t a2,
                                          uint32_t a3, uint32_t b0, uint32_t b1) {
    asm volatile(
        "mma.sync.aligned.m16n8k16.row.col.f32.bf16.bf16.f32 "
        "{%0,%1,%2,%3}, {%4,%5,%6,%7}, {%8,%9}, {%0,%1,%2,%3};"
        : "+f"(c0), "+f"(c1), "+f"(c2), "+f"(c3)
        : "r"(a0), "r"(a1), "r"(a2), "r"(a3), "r"(b0), "r"(b1));
}

// ---------------------------------------------------------------------------
// fp32 -> bf16 hi/lo converts (R13 streaming versions)
// ---------------------------------------------------------------------------
__global__ __launch_bounds__(256) void convert_a_kernel(
    const float* __restrict__ p0, const float* __restrict__ p1,
    const float* __restrict__ p2)
{
    const int z = blockIdx.z;
    const float* src = (z == 0 ? p0 : z == 1 ? p1 : p2);
    const size_t base = (size_t)z * ((size_t)M * D);
    const size_t i0 = (size_t)blockIdx.x * (256 * 16) + (size_t)threadIdx.x * 4;

    float4 v[4];
    #pragma unroll
    for (int r = 0; r < 4; r++)
        v[r] = *(const float4*)(src + i0 + (size_t)r * (256 * 4));

    #pragma unroll
    for (int r = 0; r < 4; r++) {
        const size_t i = i0 + (size_t)r * (256 * 4);
        float x[4] = {v[r].x, v[r].y, v[r].z, v[r].w};
        __nv_bfloat16 hi[4], lo[4];
        #pragma unroll
        for (int j = 0; j < 4; j++) {
            hi[j] = __float2bfloat16(x[j]);
            lo[j] = __float2bfloat16(x[j] - __bfloat162float(hi[j]));
        }
        *(uint2*)&g_Ahi[base + i] = *(uint2*)hi;
        *(uint2*)&g_Alo[base + i] = *(uint2*)lo;
    }
}

__global__ void convert_w_kernel(const float* __restrict__ w0,
                                 const float* __restrict__ w1,
                                 const float* __restrict__ w2,
                                 const float* __restrict__ w3)
{
    __shared__ float t[64][33];
    const int z = blockIdx.z;
    const float* W = z == 0 ? w0 : z == 1 ? w1 : z == 2 ? w2 : w3;
    const size_t base = (size_t)z * D * D;
    const int n0 = blockIdx.x * 32, k0 = blockIdx.y * 64;
    const int tx = threadIdx.x, ty = threadIdx.y;

    for (int i = ty; i < 64; i += 8)
        t[i][tx] = W[(size_t)(k0 + i) * D + n0 + tx];
    __syncthreads();
    for (int i = ty; i < 32; i += 8) {
        float x0 = t[2 * tx][i];
        float x1 = t[2 * tx + 1][i];
        __nv_bfloat162 h2 = __float22bfloat162_rn(make_float2(x0, x1));
        float2 hf = __bfloat1622float2(h2);
        __nv_bfloat162 l2 = __float22bfloat162_rn(
            make_float2(x0 - hf.x, x1 - hf.y));
        const size_t o = base + (size_t)(n0 + i) * D + k0 + 2 * tx;
        *(__nv_bfloat162*)&g_Bhi[o] = h2;
        *(__nv_bfloat162*)&g_Blo[o] = l2;
    }
}

// ---------------------------------------------------------------------------
// bf16 mma.sync GEMM (R6/R11/R13 configuration — best measured). UNCHANGED.
// ---------------------------------------------------------------------------
static constexpr int GBM = 128, GBN = 128, GBK = 64;
static constexpr int NC = D / GBK;
static constexpr int RSTRIDE = 144;
static constexpr int TILE_B  = 128 * RSTRIDE;
static constexpr int OA_HI = 0, OA_LO = TILE_B, OB_HI = 2 * TILE_B, OB_LO = 3 * TILE_B;
static constexpr int STG = 4 * TILE_B;
static constexpr int GEMM_SMEM = 2 * STG;          // 147456

__device__ __forceinline__ void load_tile(const __nv_bfloat16* __restrict__ src,
                                          int row0, int k0, uint32_t sdst, int tid)
{
    #pragma unroll
    for (int i = 0; i < 4; i++) {
        int unit = tid + 256 * i;
        int r = unit >> 3, c = unit & 7;
        cp16(sdst + r * RSTRIDE + c * 16,
             src + (size_t)(row0 + r) * D + k0 + c * 8);
    }
}

template <int MODE>
__global__ __launch_bounds__(256, 1) void tc_gemm_kernel(
    float* __restrict__ out_param, const float* __restrict__ bias)
{
    extern __shared__ char smc[];
    const uint32_t sb = smem_u32(smc);
    const int tid = threadIdx.x;
    const int lane = tid & 31, wid = tid >> 5;
    const int z = blockIdx.z;
    const int bm = blockIdx.y * GBM;
    const int bn = blockIdx.x * GBN;

    const __nv_bfloat16* Ahi = g_Ahi + (MODE == 0 ? (size_t)z * M * D : 0);
    const __nv_bfloat16* Alo = g_Alo + (MODE == 0 ? (size_t)z * M * D : 0);
    const __nv_bfloat16* Bhi = g_Bhi + (MODE == 0 ? (size_t)z * D * D : (size_t)3 * D * D);
    const __nv_bfloat16* Blo = g_Blo + (MODE == 0 ? (size_t)z * D * D : (size_t)3 * D * D);

    const int m_warp = (wid & 1) * 64;
    const int n_warp = (wid >> 1) * 32;

    const uint32_t a_lane = (uint32_t)((lane & 15) * RSTRIDE + ((lane >> 4) & 1) * 16);
    const uint32_t b_lane = (uint32_t)((((lane >> 4) & 1) * 8 + (lane & 7)) * RSTRIDE
                                       + ((lane >> 3) & 1) * 16);

    float acc[4][4][4];
    #pragma unroll
    for (int i = 0; i < 4; i++)
        #pragma unroll
        for (int j = 0; j < 4; j++)
            #pragma unroll
            for (int e = 0; e < 4; e++) acc[i][j][e] = 0.f;

    load_tile(Ahi, bm, 0, sb + OA_HI, tid);
    load_tile(Alo, bm, 0, sb + OA_LO, tid);
    load_tile(Bhi, bn, 0, sb + OB_HI, tid);
    load_tile(Blo, bn, 0, sb + OB_LO, tid);
    cp_commit();

    for (int c = 0; c < NC; c++) {
        const int s = c & 1;
        if (c + 1 < NC) {
            const uint32_t nb = sb + (s ^ 1) * STG;
            const int k0 = (c + 1) * GBK;
            load_tile(Ahi, bm, k0, nb + OA_HI, tid);
            load_tile(Alo, bm, k0, nb + OA_LO, tid);
            load_tile(Bhi, bn, k0, nb + OB_HI, tid);
            load_tile(Blo, bn, k0, nb + OB_LO, tid);
            cp_commit();
            cp_wait<1>();
        } else {
            cp_wait<0>();
        }
        __syncthreads();

        const uint32_t stg = sb + s * STG;
        #pragma unroll
        for (int t = 0; t < 4; t++) {
            uint32_t ah[4][4], al[4][4];
            #pragma unroll
            for (int i = 0; i < 4; i++) {
                const uint32_t ro = (uint32_t)((m_warp + i * 16) * RSTRIDE + t * 32) + a_lane;
                ldm_x4(ah[i][0], ah[i][1], ah[i][2], ah[i][3], stg + OA_HI + ro);
                ldm_x4(al[i][0], al[i][1], al[i][2], al[i][3], stg + OA_LO + ro);
            }
            uint32_t bh[8], bl[8];
            #pragma unroll
            for (int p = 0; p < 2; p++) {
                const uint32_t ro = (uint32_t)((n_warp + p * 16) * RSTRIDE + t * 32) + b_lane;
                ldm_x4(bh[p * 4 + 0], bh[p * 4 + 1], bh[p * 4 + 2], bh[p * 4 + 3],
                       stg + OB_HI + ro);
                ldm_x4(bl[p * 4 + 0], bl[p * 4 + 1], bl[p * 4 + 2], bl[p * 4 + 3],
                       stg + OB_LO + ro);
            }
            #pragma unroll
            for (int i = 0; i < 4; i++)
                #pragma unroll
                for (int j = 0; j < 4; j++) {
                    const int bi = (j >> 1) * 4 + (j & 1) * 2;
                    mma_16816(acc[i][j][0], acc[i][j][1], acc[i][j][2], acc[i][j][3],
                              ah[i][0], ah[i][1], ah[i][2], ah[i][3],
                              bh[bi], bh[bi + 1]);
                    mma_16816(acc[i][j][0], acc[i][j][1], acc[i][j][2], acc[i][j][3],
                              ah[i][0], ah[i][1], ah[i][2], ah[i][3],
                              bl[bi], bl[bi + 1]);
                    mma_16816(acc[i][j][0], acc[i][j][1], acc[i][j][2], acc[i][j][3],
                              al[i][0], al[i][1], al[i][2], al[i][3],
                              bh[bi], bh[bi + 1]);
                }
        }
        __syncthreads();
    }

    const int g = lane >> 2, tq = lane & 3;
    #pragma unroll
    for (int i = 0; i < 4; i++) {
        #pragma unroll
        for (int j = 0; j < 4; j++) {
            const int n = bn + n_warp + j * 8 + tq * 2;
            #pragma unroll
            for (int half = 0; half < 2; half++) {
                const int m = bm + m_warp + i * 16 + g + half * 8;
                float2 v = make_float2(acc[i][j][half * 2], acc[i][j][half * 2 + 1]);
                if (MODE == 0) {
                    __nv_bfloat16* dhi = z == 0 ? g_qhi : z == 1 ? g_khi : g_vhi;
                    __nv_bfloat16* dlo = z == 0 ? g_qlo : z == 1 ? g_klo : g_vlo;
                    const int bb = m >> 11, ss = m & (S - 1);
                    const int h = n >> 6, d0 = n & (DK - 1);
                    const size_t idx = ((size_t)(bb * H + h) * S + ss) * DK + d0;
                    __nv_bfloat162 hv = __float22bfloat162_rn(v);
                    float2 hf = __bfloat1622float2(hv);
                    __nv_bfloat162 lv = __float22bfloat162_rn(
                        make_float2(v.x - hf.x, v.y - hf.y));
                    *(__nv_bfloat162*)(dhi + idx) = hv;
                    *(__nv_bfloat162*)(dlo + idx) = lv;
                } else {
                    float2 bv = *(const float2*)(bias + n);
                    v.x += bv.x; v.y += bv.y;
                    *(float2*)(out_param + (size_t)m * D + n) = v;
                }
            }
        }
    }
}

// ---------------------------------------------------------------------------
// Tensor-core flash attention with 96-key tiles.
// 256 threads / 8 warps / 128 Q rows. Per-tile fixed costs (softmax phase,
// barriers, o-rescale) amortized over 1.5x more keys. exp2f softmax.
// ---------------------------------------------------------------------------
static constexpr int KR = 96;                   // keys per tile
static constexpr int RST = 144;
static constexpr int KV_TERM = KR * RST;        // 13824
static constexpr int KV_STG  = 4 * KV_TERM;     // 55296
static constexpr int ATTN_SMEM = 2 * KV_STG;    // 110592
static constexpr float SCALE_LOG2E = 0.125f * 1.4426950408889634f;

__global__ __launch_bounds__(256, 1) void flash_attn_tc()
{
    extern __shared__ char smc[];
    const uint32_t sb = smem_u32(smc);
    const int tid = threadIdx.x, lane = tid & 31, wid = tid >> 5;
    const int qb = (int)gridDim.x - 1 - (int)blockIdx.x;
    const int bh = blockIdx.y;
    const int nkeys = (qb + 1) * 128;
    const int ntiles = (nkeys + KR - 1) / KR;
    const size_t bho = (size_t)bh * S * DK;

    const __nv_bfloat16* qh_g = g_qhi + bho + (size_t)qb * 128 * DK;
    const __nv_bfloat16* ql_g = g_qlo + bho + (size_t)qb * 128 * DK;
    const __nv_bfloat16* kh_g = g_khi + bho;
    const __nv_bfloat16* kl_g = g_klo + bho;
    const __nv_bfloat16* vh_g = g_vhi + bho;
    const __nv_bfloat16* vl_g = g_vlo + bho;

    // ---- stage Q tile (128x64 hi/lo) ----
    #pragma unroll
    for (int i = 0; i < 4; i++) {
        int u = tid + 256 * i, r = u >> 3, c = u & 7;
        cp16(sb + r * RST + c * 16, qh_g + r * DK + c * 8);
        cp16(sb + 2 * KV_TERM + r * RST + c * 16, ql_g + r * DK + c * 8);
    }
    cp_commit(); cp_wait<0>(); __syncthreads();

    const uint32_t a_lane = (uint32_t)((lane & 15) * RST + (lane >> 4) * 16);
    uint32_t qh[4][4], ql[4][4];
    #pragma unroll
    for (int kt = 0; kt < 4; kt++) {
        ldm_x4(qh[kt][0], qh[kt][1], qh[kt][2], qh[kt][3],
               sb + (uint32_t)(wid * 16) * RST + kt * 32 + a_lane);
        ldm_x4(ql[kt][0], ql[kt][1], ql[kt][2], ql[kt][3],
               sb + 2 * KV_TERM + (uint32_t)(wid * 16) * RST + kt * 32 + a_lane);
    }
    __syncthreads();

    const uint32_t b_lane = (uint32_t)(((((lane >> 4) & 1) * 8) + (lane & 7)) * RST
                                       + ((lane >> 3) & 1) * 16);
    const uint32_t v_lane = (uint32_t)(((((lane >> 3) & 1) * 8) + (lane & 7)) * RST
                                       + (lane >> 4) * 16);

    // 96 rows x 8 cp16 per row = 768 units; clamp rows past S (causal-masked)
    auto load_kv = [&](int nt, uint32_t dstb) {
        const int kb0 = nt * KR;
        #pragma unroll
        for (int i = 0; i < 3; i++) {
            int u = tid + 256 * i, r = u >> 3, c = u & 7;
            int rg = kb0 + r; if (rg > S - 1) rg = S - 1;
            size_t g = (size_t)rg * DK + c * 8;
            uint32_t so = dstb + (uint32_t)(r * RST + c * 16);
            cp16(so + 0 * KV_TERM, kh_g + g);
            cp16(so + 1 * KV_TERM, kl_g + g);
            cp16(so + 2 * KV_TERM, vh_g + g);
            cp16(so + 3 * KV_TERM, vl_g + g);
        }
    };

    float o[8][4];
    #pragma unroll
    for (int j = 0; j < 8; j++)
        #pragma unroll
        for (int e = 0; e < 4; e++) o[j][e] = 0.f;
    float row_m[2] = {-1e30f, -1e30f}, row_l[2] = {0.f, 0.f};
    const int m0w = qb * 128 + wid * 16;

    load_kv(0, sb);
    cp_commit();

    for (int nt = 0; nt < ntiles; nt++) {
        if (nt + 1 < ntiles) {
            load_kv(nt + 1, sb + (uint32_t)((nt + 1) & 1) * KV_STG);
            cp_commit();
            cp_wait<1>();
        } else {
            cp_wait<0>();
        }
        __syncthreads();

        const int kbase = nt * KR;
        if (kbase <= m0w + 15) {
            const uint32_t stg = sb + (uint32_t)(nt & 1) * KV_STG;

            // ---- S = Q K^T (12 n-blocks of 8 cols) ----
            float sc[12][4];
            #pragma unroll
            for (int j = 0; j < 12; j++)
                #pragma unroll
                for (int e = 0; e < 4; e++) sc[j][e] = 0.f;

            #pragma unroll
            for (int kt = 0; kt < 4; kt++) {
                #pragma unroll
                for (int nb = 0; nb < 6; nb++) {
                    uint32_t bk[4];
                    const uint32_t tb = (uint32_t)(nb * 16) * RST + kt * 32;
                    ldm_x4(bk[0], bk[1], bk[2], bk[3], stg + tb + b_lane);  // khi
                    #pragma unroll
                    for (int j2 = 0; j2 < 2; j2++) {
                        const int j = nb * 2 + j2;
                        mma_16816(sc[j][0], sc[j][1], sc[j][2], sc[j][3],
                                  qh[kt][0], qh[kt][1], qh[kt][2], qh[kt][3],
                                  bk[j2 * 2], bk[j2 * 2 + 1]);
                        mma_16816(sc[j][0], sc[j][1], sc[j][2], sc[j][3],
                                  ql[kt][0], ql[kt][1], ql[kt][2], ql[kt][3],
                                  bk[j2 * 2], bk[j2 * 2 + 1]);
                    }
                    ldm_x4(bk[0], bk[1], bk[2], bk[3],
                           stg + KV_TERM + tb + b_lane);                    // klo
                    #pragma unroll
                    for (int j2 = 0; j2 < 2; j2++) {
                        const int j = nb * 2 + j2;
                        mma_16816(sc[j][0], sc[j][1], sc[j][2], sc[j][3],
                                  qh[kt][0], qh[kt][1], qh[kt][2], qh[kt][3],
                                  bk[j2 * 2], bk[j2 * 2 + 1]);
                    }
                }
            }

            // scale (log2e folded) + causal mask
            const bool needm = (kbase + KR - 1) > m0w;
            #pragma unroll
            for (int j = 0; j < 12; j++)
                #pragma unroll
                for (int e = 0; e < 4; e++) {
                    float x = sc[j][e] * SCALE_LOG2E;
                    if (needm) {
                        const int key = kbase + j * 8 + (lane & 3) * 2 + (e & 1);
                        const int row = m0w + (lane >> 2) + (e >> 1) * 8;
                        if (key > row) x = -1e30f;
                    }
                    sc[j][e] = x;
                }

            // ---- online softmax (base-2 domain) ----
            #pragma unroll
            for (int h2 = 0; h2 < 2; h2++) {
                float mx = -1e30f;
                #pragma unroll
                for (int j = 0; j < 12; j++)
                    mx = fmaxf(mx, fmaxf(sc[j][h2 * 2], sc[j][h2 * 2 + 1]));
                mx = fmaxf(mx, __shfl_xor_sync(0xffffffffu, mx, 1));
                mx = fmaxf(mx, __shfl_xor_sync(0xffffffffu, mx, 2));
                const float mn = fmaxf(row_m[h2], mx);
                const float corr = exp2f(row_m[h2] - mn);
                float sum = 0.f;
                #pragma unroll
                for (int j = 0; j < 12; j++) {
                    float p0 = exp2f(sc[j][h2 * 2] - mn);
                    float p1 = exp2f(sc[j][h2 * 2 + 1] - mn);
                    sc[j][h2 * 2] = p0; sc[j][h2 * 2 + 1] = p1;
                    sum += p0 + p1;
                }
                sum += __shfl_xor_sync(0xffffffffu, sum, 1);
                sum += __shfl_xor_sync(0xffffffffu, sum, 2);
                row_l[h2] = row_l[h2] * corr + sum;
                row_m[h2] = mn;
                #pragma unroll
                for (int j = 0; j < 8; j++) {
                    o[j][h2 * 2] *= corr;
                    o[j][h2 * 2 + 1] *= corr;
                }
            }

            // ---- pack P into bf16 hi/lo A-fragments ----
            uint32_t pHi[12][2], pLo[12][2];
            #pragma unroll
            for (int j = 0; j < 12; j++)
                #pragma unroll
                for (int pr = 0; pr < 2; pr++) {
                    float p0 = sc[j][pr * 2], p1 = sc[j][pr * 2 + 1];
                    __nv_bfloat162 hv = __float22bfloat162_rn(make_float2(p0, p1));
                    float2 hf = __bfloat1622float2(hv);
                    __nv_bfloat162 lv = __float22bfloat162_rn(
                        make_float2(p0 - hf.x, p1 - hf.y));
                    pHi[j][pr] = *(uint32_t*)&hv;
                    pLo[j][pr] = *(uint32_t*)&lv;
                }

            // ---- O += P V (6 k16 steps over 96 keys) ----
            #pragma unroll
            for (int kt = 0; kt < 6; kt++) {
                const uint32_t ah0 = pHi[2 * kt][0], ah1 = pHi[2 * kt][1];
                const uint32_t ah2 = pHi[2 * kt + 1][0], ah3 = pHi[2 * kt + 1][1];
                const uint32_t al0 = pLo[2 * kt][0], al1 = pLo[2 * kt][1];
                const uint32_t al2 = pLo[2 * kt + 1][0], al3 = pLo[2 * kt + 1][1];
                #pragma unroll
                for (int nb = 0; nb < 4; nb++) {
                    uint32_t bv[4];
                    const uint32_t tb = (uint32_t)(kt * 16) * RST + nb * 32;
                    ldm_x4_t(bv[0], bv[1], bv[2], bv[3],
                             stg + 2 * KV_TERM + tb + v_lane);               // vhi
                    #pragma unroll
                    for (int j2 = 0; j2 < 2; j2++) {
                        const int j = nb * 2 + j2;
                        mma_16816(o[j][0], o[j][1], o[j][2], o[j][3],
                                  ah0, ah1, ah2, ah3, bv[j2 * 2], bv[j2 * 2 + 1]);
                        mma_16816(o[j][0], o[j][1], o[j][2], o[j][3],
                                  al0, al1, al2, al3, bv[j2 * 2], bv[j2 * 2 + 1]);
                    }
                    ldm_x4_t(bv[0], bv[1], bv[2], bv[3],
                             stg + 3 * KV_TERM + tb + v_lane);               // vlo
                    #pragma unroll
                    for (int j2 = 0; j2 < 2; j2++) {
                        const int j = nb * 2 + j2;
                        mma_16816(o[j][0], o[j][1], o[j][2], o[j][3],
                                  ah0, ah1, ah2, ah3, bv[j2 * 2], bv[j2 * 2 + 1]);
                    }
                }
            }
        }
        __syncthreads();
    }

    // ---- epilogue: normalize + bf16 hi/lo split into out-proj A ----
    const int b = bh >> 4, head = bh & (H - 1);
    #pragma unroll
    for (int h2 = 0; h2 < 2; h2++) {
        const float inv = 1.0f / row_l[h2];
        const int row = m0w + (lane >> 2) + h2 * 8;
        #pragma unroll
        for (int j = 0; j < 8; j++) {
            const int col = head * DK + j * 8 + (lane & 3) * 2;
            const size_t idx = (size_t)(b * S + row) * D + col;
            float2 v = make_float2(o[j][h2 * 2] * inv, o[j][h2 * 2 + 1] * inv);
            __nv_bfloat162 hv = __float22bfloat162_rn(v);
            float2 hf = __bfloat1622float2(hv);
            __nv_bfloat162 lv = __float22bfloat162_rn(
                make_float2(v.x - hf.x, v.y - hf.y));
            *(__nv_bfloat162*)(g_Ahi + idx) = hv;
            *(__nv_bfloat162*)(g_Alo + idx) = lv;
        }
    }
}

// ---------------------------------------------------------------------------
extern "C" void kernel_launch(void* const* d_in, const int* in_sizes, int n_in,
                              void* d_out, int out_size)
{
    const float* Q  = (const float*)d_in[0];
    const float* K  = (const float*)d_in[1];
    const float* V  = (const float*)d_in[2];
    const float* Wq = (const float*)d_in[3];
    const float* Wk = (const float*)d_in[4];
    const float* Wv = (const float*)d_in[5];
    const float* Wo = (const float*)d_in[6];
    const float* bo = (const float*)d_in[7];
    float* out = (float*)d_out;

    (void)in_sizes; (void)n_in; (void)out_size;

    cudaFuncSetAttribute(tc_gemm_kernel<0>,
                         cudaFuncAttributeMaxDynamicSharedMemorySize, GEMM_SMEM);
    cudaFuncSetAttribute(tc_gemm_kernel<1>,
                         cudaFuncAttributeMaxDynamicSharedMemorySize, GEMM_SMEM);
    cudaFuncSetAttribute(flash_attn_tc,
                         cudaFuncAttributeMaxDynamicSharedMemorySize, ATTN_SMEM);

    convert_a_kernel<<<dim3(M * D / (256 * 16), 1, 3), 256>>>(Q, K, V);
    convert_w_kernel<<<dim3(D / 32, D / 64, 4), dim3(32, 8)>>>(Wq, Wk, Wv, Wo);

    tc_gemm_kernel<0><<<dim3(D / GBN, M / GBM, 3), 256, GEMM_SMEM>>>(nullptr, nullptr);

    flash_attn_tc<<<dim3(S / 128, B * H), 256, ATTN_SMEM>>>();

    tc_gemm_kernel<1><<<dim3(D / GBN, M / GBM, 1), 256, GEMM_SMEM>>>(out, bo);
}

// round 15
// speedup vs baseline: 1.0739x; 1.0188x over previous
#include <cuda_runtime.h>
#include <cuda_bf16.h>
#include <cstdint>

// Problem constants
static constexpr int B  = 2;
static constexpr int S  = 2048;
static constexpr int D  = 1024;
static constexpr int H  = 16;
static constexpr int DK = 64;
static constexpr int M  = B * S;   // 4096

// ---------------------------------------------------------------------------
// Device scratch
// ---------------------------------------------------------------------------
__device__ __nv_bfloat16 g_qhi[(size_t)B * H * S * DK];
__device__ __nv_bfloat16 g_qlo[(size_t)B * H * S * DK];
__device__ __nv_bfloat16 g_khi[(size_t)B * H * S * DK];
__device__ __nv_bfloat16 g_klo[(size_t)B * H * S * DK];
__device__ __nv_bfloat16 g_vhi[(size_t)B * H * S * DK];
__device__ __nv_bfloat16 g_vlo[(size_t)B * H * S * DK];

__device__ __nv_bfloat16 g_Ahi[3 * (size_t)M * D];
__device__ __nv_bfloat16 g_Alo[3 * (size_t)M * D];
__device__ __nv_bfloat16 g_Bhi[4 * (size_t)D * D];
__device__ __nv_bfloat16 g_Blo[4 * (size_t)D * D];

// ---------------------------------------------------------------------------
// PTX helpers
// ---------------------------------------------------------------------------
__device__ __forceinline__ uint32_t smem_u32(const void* p) {
    uint32_t a;
    asm("{ .reg .u64 t; cvta.to.shared.u64 t, %1; cvt.u32.u64 %0, t; }"
        : "=r"(a) : "l"(p));
    return a;
}
__device__ __forceinline__ void cp16(uint32_t saddr, const void* g) {
    asm volatile("cp.async.cg.shared.global [%0], [%1], 16;"
                 :: "r"(saddr), "l"(g) : "memory");
}
__device__ __forceinline__ void cp_commit() {
    asm volatile("cp.async.commit_group;" ::: "memory");
}
template <int N>
__device__ __forceinline__ void cp_wait() {
    asm volatile("cp.async.wait_group %0;" :: "n"(N) : "memory");
}
__device__ __forceinline__ void ldm_x4(uint32_t& r0, uint32_t& r1,
                                       uint32_t& r2, uint32_t& r3, uint32_t a) {
    asm volatile("ldmatrix.sync.aligned.m8n8.x4.shared.b16 {%0,%1,%2,%3}, [%4];"
                 : "=r"(r0), "=r"(r1), "=r"(r2), "=r"(r3) : "r"(a));
}
__device__ __forceinline__ void ldm_x4_t(uint32_t& r0, uint32_t& r1,
                                         uint32_t& r2, uint32_t& r3, uint32_t a) {
    asm volatile("ldmatrix.sync.aligned.m8n8.x4.trans.shared.b16 {%0,%1,%2,%3}, [%4];"
                 : "=r"(r0), "=r"(r1), "=r"(r2), "=r"(r3) : "r"(a));
}
__device__ __forceinline__ void mma_16816(float& c0, float& c1, float& c2, float& c3,
                                          uint32_t a0, uint32_t a1, uint32_t a2,
                                          uint32_t a3, uint32_t b0, uint32_t b1) {
    asm volatile(
        "mma.sync.aligned.m16n8k16.row.col.f32.bf16.bf16.f32 "
        "{%0,%1,%2,%3}, {%4,%5,%6,%7}, {%8,%9}, {%0,%1,%2,%3};"
        : "+f"(c0), "+f"(c1), "+f"(c2), "+f"(c3)
        : "r"(a0), "r"(a1), "r"(a2), "r"(a3), "r"(b0), "r"(b1));
}

// ---------------------------------------------------------------------------
// fp32 -> bf16 hi/lo converts (R13 streaming versions)
// ---------------------------------------------------------------------------
__global__ __launch_bounds__(256) void convert_a_kernel(
    const float* __restrict__ p0, const float* __restrict__ p1,
    const float* __restrict__ p2)
{
    const int z = blockIdx.z;
    const float* src = (z == 0 ? p0 : z == 1 ? p1 : p2);
    const size_t base = (size_t)z * ((size_t)M * D);
    const size_t i0 = (size_t)blockIdx.x * (256 * 16) + (size_t)threadIdx.x * 4;

    float4 v[4];
    #pragma unroll
    for (int r = 0; r < 4; r++)
        v[r] = *(const float4*)(src + i0 + (size_t)r * (256 * 4));

    #pragma unroll
    for (int r = 0; r < 4; r++) {
        const size_t i = i0 + (size_t)r * (256 * 4);
        float x[4] = {v[r].x, v[r].y, v[r].z, v[r].w};
        __nv_bfloat16 hi[4], lo[4];
        #pragma unroll
        for (int j = 0; j < 4; j++) {
            hi[j] = __float2bfloat16(x[j]);
            lo[j] = __float2bfloat16(x[j] - __bfloat162float(hi[j]));
        }
        *(uint2*)&g_Ahi[base + i] = *(uint2*)hi;
        *(uint2*)&g_Alo[base + i] = *(uint2*)lo;
    }
}

__global__ void convert_w_kernel(const float* __restrict__ w0,
                                 const float* __restrict__ w1,
                                 const float* __restrict__ w2,
                                 const float* __restrict__ w3)
{
    __shared__ float t[64][33];
    const int z = blockIdx.z;
    const float* W = z == 0 ? w0 : z == 1 ? w1 : z == 2 ? w2 : w3;
    const size_t base = (size_t)z * D * D;
    const int n0 = blockIdx.x * 32, k0 = blockIdx.y * 64;
    const int tx = threadIdx.x, ty = threadIdx.y;

    for (int i = ty; i < 64; i += 8)
        t[i][tx] = W[(size_t)(k0 + i) * D + n0 + tx];
    __syncthreads();
    for (int i = ty; i < 32; i += 8) {
        float x0 = t[2 * tx][i];
        float x1 = t[2 * tx + 1][i];
        __nv_bfloat162 h2 = __float22bfloat162_rn(make_float2(x0, x1));
        float2 hf = __bfloat1622float2(h2);
        __nv_bfloat162 l2 = __float22bfloat162_rn(
            make_float2(x0 - hf.x, x1 - hf.y));
        const size_t o = base + (size_t)(n0 + i) * D + k0 + 2 * tx;
        *(__nv_bfloat162*)&g_Bhi[o] = h2;
        *(__nv_bfloat162*)&g_Blo[o] = l2;
    }
}

// ---------------------------------------------------------------------------
// Shared GEMM constants
// ---------------------------------------------------------------------------
static constexpr int GBM = 128, GBN = 128, GBK = 64;
static constexpr int NC = D / GBK;                 // 16 chunks
static constexpr int RSTRIDE = 144;                // 128B data + 16B pad
static constexpr int TILE_B  = 128 * RSTRIDE;      // 18432  (128-row tile)
static constexpr int HTILE_B = 64 * RSTRIDE;       // 9216   (64-row tile)

// 128-row tile loader (1024 cp16 units)
__device__ __forceinline__ void load_tile(const __nv_bfloat16* __restrict__ src,
                                          int row0, int k0, uint32_t sdst, int tid)
{
    #pragma unroll
    for (int i = 0; i < 4; i++) {
        int unit = tid + 256 * i;
        int r = unit >> 3, c = unit & 7;
        cp16(sdst + r * RSTRIDE + c * 16,
             src + (size_t)(row0 + r) * D + k0 + c * 8);
    }
}
// 64-row tile loader (512 cp16 units)
__device__ __forceinline__ void load_tile64(const __nv_bfloat16* __restrict__ src,
                                            int row0, int k0, uint32_t sdst, int tid)
{
    #pragma unroll
    for (int i = 0; i < 2; i++) {
        int unit = tid + 256 * i;
        int r = unit >> 3, c = unit & 7;
        cp16(sdst + r * RSTRIDE + c * 16,
             src + (size_t)(row0 + r) * D + k0 + c * 8);
    }
}

// ---------------------------------------------------------------------------
// qkv GEMM: CTA 128x64 tiles (1536 CTAs -> 6% wave imbalance vs 15.6%).
// 8 warps as 4m x 2n (32x32 warp tiles), BK=64 2-stage, 3-term split.
// Epilogue scatters bf16 hi/lo q/k/v to [B,H,S,DK].
// ---------------------------------------------------------------------------
static constexpr int QOA_HI = 0, QOA_LO = TILE_B;
static constexpr int QOB_HI = 2 * TILE_B, QOB_LO = 2 * TILE_B + HTILE_B;
static constexpr int QSTG = 2 * TILE_B + 2 * HTILE_B;   // 55296
static constexpr int QKV_SMEM = 2 * QSTG;               // 110592

__global__ __launch_bounds__(256, 1) void tc_gemm_qkv()
{
    extern __shared__ char smc[];
    const uint32_t sb = smem_u32(smc);
    const int tid = threadIdx.x;
    const int lane = tid & 31, wid = tid >> 5;
    const int z = blockIdx.z;
    const int bm = blockIdx.y * GBM;
    const int bn = blockIdx.x * 64;

    const __nv_bfloat16* Ahi = g_Ahi + (size_t)z * M * D;
    const __nv_bfloat16* Alo = g_Alo + (size_t)z * M * D;
    const __nv_bfloat16* Bhi = g_Bhi + (size_t)z * D * D;
    const __nv_bfloat16* Blo = g_Blo + (size_t)z * D * D;

    const int m_warp = (wid & 3) * 32;     // 4 m positions
    const int n_warp = (wid >> 2) * 32;    // 2 n positions

    const uint32_t a_lane = (uint32_t)((lane & 15) * RSTRIDE + ((lane >> 4) & 1) * 16);
    const uint32_t b_lane = (uint32_t)((((lane >> 4) & 1) * 8 + (lane & 7)) * RSTRIDE
                                       + ((lane >> 3) & 1) * 16);

    float acc[2][4][4];
    #pragma unroll
    for (int i = 0; i < 2; i++)
        #pragma unroll
        for (int j = 0; j < 4; j++)
            #pragma unroll
            for (int e = 0; e < 4; e++) acc[i][j][e] = 0.f;

    load_tile(Ahi, bm, 0, sb + QOA_HI, tid);
    load_tile(Alo, bm, 0, sb + QOA_LO, tid);
    load_tile64(Bhi, bn, 0, sb + QOB_HI, tid);
    load_tile64(Blo, bn, 0, sb + QOB_LO, tid);
    cp_commit();

    for (int c = 0; c < NC; c++) {
        const int s = c & 1;
        if (c + 1 < NC) {
            const uint32_t nb = sb + (s ^ 1) * QSTG;
            const int k0 = (c + 1) * GBK;
            load_tile(Ahi, bm, k0, nb + QOA_HI, tid);
            load_tile(Alo, bm, k0, nb + QOA_LO, tid);
            load_tile64(Bhi, bn, k0, nb + QOB_HI, tid);
            load_tile64(Blo, bn, k0, nb + QOB_LO, tid);
            cp_commit();
            cp_wait<1>();
        } else {
            cp_wait<0>();
        }
        __syncthreads();

        const uint32_t stg = sb + s * QSTG;
        #pragma unroll
        for (int t = 0; t < 4; t++) {
            uint32_t ah[2][4], al[2][4];
            #pragma unroll
            for (int i = 0; i < 2; i++) {
                const uint32_t ro = (uint32_t)((m_warp + i * 16) * RSTRIDE + t * 32) + a_lane;
                ldm_x4(ah[i][0], ah[i][1], ah[i][2], ah[i][3], stg + QOA_HI + ro);
                ldm_x4(al[i][0], al[i][1], al[i][2], al[i][3], stg + QOA_LO + ro);
            }
            uint32_t bh[8], bl[8];
            #pragma unroll
            for (int p = 0; p < 2; p++) {
                const uint32_t ro = (uint32_t)((n_warp + p * 16) * RSTRIDE + t * 32) + b_lane;
                ldm_x4(bh[p * 4 + 0], bh[p * 4 + 1], bh[p * 4 + 2], bh[p * 4 + 3],
                       stg + QOB_HI + ro);
                ldm_x4(bl[p * 4 + 0], bl[p * 4 + 1], bl[p * 4 + 2], bl[p * 4 + 3],
                       stg + QOB_LO + ro);
            }
            #pragma unroll
            for (int i = 0; i < 2; i++)
                #pragma unroll
                for (int j = 0; j < 4; j++) {
                    const int bi = (j >> 1) * 4 + (j & 1) * 2;
                    mma_16816(acc[i][j][0], acc[i][j][1], acc[i][j][2], acc[i][j][3],
                              ah[i][0], ah[i][1], ah[i][2], ah[i][3],
                              bh[bi], bh[bi + 1]);
                    mma_16816(acc[i][j][0], acc[i][j][1], acc[i][j][2], acc[i][j][3],
                              ah[i][0], ah[i][1], ah[i][2], ah[i][3],
                              bl[bi], bl[bi + 1]);
                    mma_16816(acc[i][j][0], acc[i][j][1], acc[i][j][2], acc[i][j][3],
                              al[i][0], al[i][1], al[i][2], al[i][3],
                              bh[bi], bh[bi + 1]);
                }
        }
        __syncthreads();
    }

    // Epilogue: scatter bf16 hi/lo to [B,H,S,DK]
    const int g = lane >> 2, tq = lane & 3;
    __nv_bfloat16* dhi = z == 0 ? g_qhi : z == 1 ? g_khi : g_vhi;
    __nv_bfloat16* dlo = z == 0 ? g_qlo : z == 1 ? g_klo : g_vlo;
    #pragma unroll
    for (int i = 0; i < 2; i++) {
        #pragma unroll
        for (int j = 0; j < 4; j++) {
            const int n = bn + n_warp + j * 8 + tq * 2;
            #pragma unroll
            for (int half = 0; half < 2; half++) {
                const int m = bm + m_warp + i * 16 + g + half * 8;
                float2 v = make_float2(acc[i][j][half * 2], acc[i][j][half * 2 + 1]);
                const int bb = m >> 11, ss = m & (S - 1);
                const int h = n >> 6, d0 = n & (DK - 1);
                const size_t idx = ((size_t)(bb * H + h) * S + ss) * DK + d0;
                __nv_bfloat162 hv = __float22bfloat162_rn(v);
                float2 hf = __bfloat1622float2(hv);
                __nv_bfloat162 lv = __float22bfloat162_rn(
                    make_float2(v.x - hf.x, v.y - hf.y));
                *(__nv_bfloat162*)(dhi + idx) = hv;
                *(__nv_bfloat162*)(dlo + idx) = lv;
            }
        }
    }
}

// ---------------------------------------------------------------------------
// Out-projection GEMM (R6/R13 128x128 configuration — unchanged).
// ---------------------------------------------------------------------------
static constexpr int OA_HI = 0, OA_LO = TILE_B, OB_HI = 2 * TILE_B, OB_LO = 3 * TILE_B;
static constexpr int STG = 4 * TILE_B;             // 73728
static constexpr int GEMM_SMEM = 2 * STG;          // 147456

__global__ __launch_bounds__(256, 1) void tc_gemm_out(
    float* __restrict__ out_param, const float* __restrict__ bias)
{
    extern __shared__ char smc[];
    const uint32_t sb = smem_u32(smc);
    const int tid = threadIdx.x;
    const int lane = tid & 31, wid = tid >> 5;
    const int bm = blockIdx.y * GBM;
    const int bn = blockIdx.x * GBN;

    const __nv_bfloat16* Ahi = g_Ahi;
    const __nv_bfloat16* Alo = g_Alo;
    const __nv_bfloat16* Bhi = g_Bhi + (size_t)3 * D * D;
    const __nv_bfloat16* Blo = g_Blo + (size_t)3 * D * D;

    const int m_warp = (wid & 1) * 64;
    const int n_warp = (wid >> 1) * 32;

    const uint32_t a_lane = (uint32_t)((lane & 15) * RSTRIDE + ((lane >> 4) & 1) * 16);
    const uint32_t b_lane = (uint32_t)((((lane >> 4) & 1) * 8 + (lane & 7)) * RSTRIDE
                                       + ((lane >> 3) & 1) * 16);

    float acc[4][4][4];
    #pragma unroll
    for (int i = 0; i < 4; i++)
        #pragma unroll
        for (int j = 0; j < 4; j++)
            #pragma unroll
            for (int e = 0; e < 4; e++) acc[i][j][e] = 0.f;

    load_tile(Ahi, bm, 0, sb + OA_HI, tid);
    load_tile(Alo, bm, 0, sb + OA_LO, tid);
    load_tile(Bhi, bn, 0, sb + OB_HI, tid);
    load_tile(Blo, bn, 0, sb + OB_LO, tid);
    cp_commit();

    for (int c = 0; c < NC; c++) {
        const int s = c & 1;
        if (c + 1 < NC) {
            const uint32_t nb = sb + (s ^ 1) * STG;
            const int k0 = (c + 1) * GBK;
            load_tile(Ahi, bm, k0, nb + OA_HI, tid);
            load_tile(Alo, bm, k0, nb + OA_LO, tid);
            load_tile(Bhi, bn, k0, nb + OB_HI, tid);
            load_tile(Blo, bn, k0, nb + OB_LO, tid);
            cp_commit();
            cp_wait<1>();
        } else {
            cp_wait<0>();
        }
        __syncthreads();

        const uint32_t stg = sb + s * STG;
        #pragma unroll
        for (int t = 0; t < 4; t++) {
            uint32_t ah[4][4], al[4][4];
            #pragma unroll
            for (int i = 0; i < 4; i++) {
                const uint32_t ro = (uint32_t)((m_warp + i * 16) * RSTRIDE + t * 32) + a_lane;
                ldm_x4(ah[i][0], ah[i][1], ah[i][2], ah[i][3], stg + OA_HI + ro);
                ldm_x4(al[i][0], al[i][1], al[i][2], al[i][3], stg + OA_LO + ro);
            }
            uint32_t bh[8], bl[8];
            #pragma unroll
            for (int p = 0; p < 2; p++) {
                const uint32_t ro = (uint32_t)((n_warp + p * 16) * RSTRIDE + t * 32) + b_lane;
                ldm_x4(bh[p * 4 + 0], bh[p * 4 + 1], bh[p * 4 + 2], bh[p * 4 + 3],
                       stg + OB_HI + ro);
                ldm_x4(bl[p * 4 + 0], bl[p * 4 + 1], bl[p * 4 + 2], bl[p * 4 + 3],
                       stg + OB_LO + ro);
            }
            #pragma unroll
            for (int i = 0; i < 4; i++)
                #pragma unroll
                for (int j = 0; j < 4; j++) {
                    const int bi = (j >> 1) * 4 + (j & 1) * 2;
                    mma_16816(acc[i][j][0], acc[i][j][1], acc[i][j][2], acc[i][j][3],
                              ah[i][0], ah[i][1], ah[i][2], ah[i][3],
                              bh[bi], bh[bi + 1]);
                    mma_16816(acc[i][j][0], acc[i][j][1], acc[i][j][2], acc[i][j][3],
                              ah[i][0], ah[i][1], ah[i][2], ah[i][3],
                              bl[bi], bl[bi + 1]);
                    mma_16816(acc[i][j][0], acc[i][j][1], acc[i][j][2], acc[i][j][3],
                              al[i][0], al[i][1], al[i][2], al[i][3],
                              bh[bi], bh[bi + 1]);
                }
        }
        __syncthreads();
    }

    const int g = lane >> 2, tq = lane & 3;
    #pragma unroll
    for (int i = 0; i < 4; i++) {
        #pragma unroll
        for (int j = 0; j < 4; j++) {
            const int n = bn + n_warp + j * 8 + tq * 2;
            #pragma unroll
            for (int half = 0; half < 2; half++) {
                const int m = bm + m_warp + i * 16 + g + half * 8;
                float2 v = make_float2(acc[i][j][half * 2], acc[i][j][half * 2 + 1]);
                float2 bv = *(const float2*)(bias + n);
                v.x += bv.x; v.y += bv.y;
                *(float2*)(out_param + (size_t)m * D + n) = v;
            }
        }
    }
}

// ---------------------------------------------------------------------------
// Tensor-core flash attention (R14 configuration — 96-key tiles, exp2f).
// ---------------------------------------------------------------------------
static constexpr int KR = 96;
static constexpr int RST = 144;
static constexpr int KV_TERM = KR * RST;        // 13824
static constexpr int KV_STG  = 4 * KV_TERM;     // 55296
static constexpr int ATTN_SMEM = 2 * KV_STG;    // 110592
static constexpr float SCALE_LOG2E = 0.125f * 1.4426950408889634f;

__global__ __launch_bounds__(256, 1) void flash_attn_tc()
{
    extern __shared__ char smc[];
    const uint32_t sb = smem_u32(smc);
    const int tid = threadIdx.x, lane = tid & 31, wid = tid >> 5;
    const int qb = (int)gridDim.x - 1 - (int)blockIdx.x;
    const int bh = blockIdx.y;
    const int nkeys = (qb + 1) * 128;
    const int ntiles = (nkeys + KR - 1) / KR;
    const size_t bho = (size_t)bh * S * DK;

    const __nv_bfloat16* qh_g = g_qhi + bho + (size_t)qb * 128 * DK;
    const __nv_bfloat16* ql_g = g_qlo + bho + (size_t)qb * 128 * DK;
    const __nv_bfloat16* kh_g = g_khi + bho;
    const __nv_bfloat16* kl_g = g_klo + bho;
    const __nv_bfloat16* vh_g = g_vhi + bho;
    const __nv_bfloat16* vl_g = g_vlo + bho;

    #pragma unroll
    for (int i = 0; i < 4; i++) {
        int u = tid + 256 * i, r = u >> 3, c = u & 7;
        cp16(sb + r * RST + c * 16, qh_g + r * DK + c * 8);
        cp16(sb + 2 * KV_TERM + r * RST + c * 16, ql_g + r * DK + c * 8);
    }
    cp_commit(); cp_wait<0>(); __syncthreads();

    const uint32_t a_lane = (uint32_t)((lane & 15) * RST + (lane >> 4) * 16);
    uint32_t qh[4][4], ql[4][4];
    #pragma unroll
    for (int kt = 0; kt < 4; kt++) {
        ldm_x4(qh[kt][0], qh[kt][1], qh[kt][2], qh[kt][3],
               sb + (uint32_t)(wid * 16) * RST + kt * 32 + a_lane);
        ldm_x4(ql[kt][0], ql[kt][1], ql[kt][2], ql[kt][3],
               sb + 2 * KV_TERM + (uint32_t)(wid * 16) * RST + kt * 32 + a_lane);
    }
    __syncthreads();

    const uint32_t b_lane = (uint32_t)(((((lane >> 4) & 1) * 8) + (lane & 7)) * RST
                                       + ((lane >> 3) & 1) * 16);
    const uint32_t v_lane = (uint32_t)(((((lane >> 3) & 1) * 8) + (lane & 7)) * RST
                                       + (lane >> 4) * 16);

    auto load_kv = [&](int nt, uint32_t dstb) {
        const int kb0 = nt * KR;
        #pragma unroll
        for (int i = 0; i < 3; i++) {
            int u = tid + 256 * i, r = u >> 3, c = u & 7;
            int rg = kb0 + r; if (rg > S - 1) rg = S - 1;
            size_t g = (size_t)rg * DK + c * 8;
            uint32_t so = dstb + (uint32_t)(r * RST + c * 16);
            cp16(so + 0 * KV_TERM, kh_g + g);
            cp16(so + 1 * KV_TERM, kl_g + g);
            cp16(so + 2 * KV_TERM, vh_g + g);
            cp16(so + 3 * KV_TERM, vl_g + g);
        }
    };

    float o[8][4];
    #pragma unroll
    for (int j = 0; j < 8; j++)
        #pragma unroll
        for (int e = 0; e < 4; e++) o[j][e] = 0.f;
    float row_m[2] = {-1e30f, -1e30f}, row_l[2] = {0.f, 0.f};
    const int m0w = qb * 128 + wid * 16;

    load_kv(0, sb);
    cp_commit();

    for (int nt = 0; nt < ntiles; nt++) {
        if (nt + 1 < ntiles) {
            load_kv(nt + 1, sb + (uint32_t)((nt + 1) & 1) * KV_STG);
            cp_commit();
            cp_wait<1>();
        } else {
            cp_wait<0>();
        }
        __syncthreads();

        const int kbase = nt * KR;
        if (kbase <= m0w + 15) {
            const uint32_t stg = sb + (uint32_t)(nt & 1) * KV_STG;

            float sc[12][4];
            #pragma unroll
            for (int j = 0; j < 12; j++)
                #pragma unroll
                for (int e = 0; e < 4; e++) sc[j][e] = 0.f;

            #pragma unroll
            for (int kt = 0; kt < 4; kt++) {
                #pragma unroll
                for (int nb = 0; nb < 6; nb++) {
                    uint32_t bk[4];
                    const uint32_t tb = (uint32_t)(nb * 16) * RST + kt * 32;
                    ldm_x4(bk[0], bk[1], bk[2], bk[3], stg + tb + b_lane);  // khi
                    #pragma unroll
                    for (int j2 = 0; j2 < 2; j2++) {
                        const int j = nb * 2 + j2;
                        mma_16816(sc[j][0], sc[j][1], sc[j][2], sc[j][3],
                                  qh[kt][0], qh[kt][1], qh[kt][2], qh[kt][3],
                                  bk[j2 * 2], bk[j2 * 2 + 1]);
                        mma_16816(sc[j][0], sc[j][1], sc[j][2], sc[j][3],
                                  ql[kt][0], ql[kt][1], ql[kt][2], ql[kt][3],
                                  bk[j2 * 2], bk[j2 * 2 + 1]);
                    }
                    ldm_x4(bk[0], bk[1], bk[2], bk[3],
                           stg + KV_TERM + tb + b_lane);                    // klo
                    #pragma unroll
                    for (int j2 = 0; j2 < 2; j2++) {
                        const int j = nb * 2 + j2;
                        mma_16816(sc[j][0], sc[j][1], sc[j][2], sc[j][3],
                                  qh[kt][0], qh[kt][1], qh[kt][2], qh[kt][3],
                                  bk[j2 * 2], bk[j2 * 2 + 1]);
                    }
                }
            }

            const bool needm = (kbase + KR - 1) > m0w;
            #pragma unroll
            for (int j = 0; j < 12; j++)
                #pragma unroll
                for (int e = 0; e < 4; e++) {
                    float x = sc[j][e] * SCALE_LOG2E;
                    if (needm) {
                        const int key = kbase + j * 8 + (lane & 3) * 2 + (e & 1);
                        const int row = m0w + (lane >> 2) + (e >> 1) * 8;
                        if (key > row) x = -1e30f;
                    }
                    sc[j][e] = x;
                }

            #pragma unroll
            for (int h2 = 0; h2 < 2; h2++) {
                float mx = -1e30f;
                #pragma unroll
                for (int j = 0; j < 12; j++)
                    mx = fmaxf(mx, fmaxf(sc[j][h2 * 2], sc[j][h2 * 2 + 1]));
                mx = fmaxf(mx, __shfl_xor_sync(0xffffffffu, mx, 1));
                mx = fmaxf(mx, __shfl_xor_sync(0xffffffffu, mx, 2));
                const float mn = fmaxf(row_m[h2], mx);
                const float corr = exp2f(row_m[h2] - mn);
                float sum = 0.f;
                #pragma unroll
                for (int j = 0; j < 12; j++) {
                    float p0 = exp2f(sc[j][h2 * 2] - mn);
                    float p1 = exp2f(sc[j][h2 * 2 + 1] - mn);
                    sc[j][h2 * 2] = p0; sc[j][h2 * 2 + 1] = p1;
                    sum += p0 + p1;
                }
                sum += __shfl_xor_sync(0xffffffffu, sum, 1);
                sum += __shfl_xor_sync(0xffffffffu, sum, 2);
                row_l[h2] = row_l[h2] * corr + sum;
                row_m[h2] = mn;
                #pragma unroll
                for (int j = 0; j < 8; j++) {
                    o[j][h2 * 2] *= corr;
                    o[j][h2 * 2 + 1] *= corr;
                }
            }

            uint32_t pHi[12][2], pLo[12][2];
            #pragma unroll
            for (int j = 0; j < 12; j++)
                #pragma unroll
                for (int pr = 0; pr < 2; pr++) {
                    float p0 = sc[j][pr * 2], p1 = sc[j][pr * 2 + 1];
                    __nv_bfloat162 hv = __float22bfloat162_rn(make_float2(p0, p1));
                    float2 hf = __bfloat1622float2(hv);
                    __nv_bfloat162 lv = __float22bfloat162_rn(
                        make_float2(p0 - hf.x, p1 - hf.y));
                    pHi[j][pr] = *(uint32_t*)&hv;
                    pLo[j][pr] = *(uint32_t*)&lv;
                }

            #pragma unroll
            for (int kt = 0; kt < 6; kt++) {
                const uint32_t ah0 = pHi[2 * kt][0], ah1 = pHi[2 * kt][1];
                const uint32_t ah2 = pHi[2 * kt + 1][0], ah3 = pHi[2 * kt + 1][1];
                const uint32_t al0 = pLo[2 * kt][0], al1 = pLo[2 * kt][1];
                const uint32_t al2 = pLo[2 * kt + 1][0], al3 = pLo[2 * kt + 1][1];
                #pragma unroll
                for (int nb = 0; nb < 4; nb++) {
                    uint32_t bv[4];
                    const uint32_t tb = (uint32_t)(kt * 16) * RST + nb * 32;
                    ldm_x4_t(bv[0], bv[1], bv[2], bv[3],
                             stg + 2 * KV_TERM + tb + v_lane);               // vhi
                    #pragma unroll
                    for (int j2 = 0; j2 < 2; j2++) {
                        const int j = nb * 2 + j2;
                        mma_16816(o[j][0], o[j][1], o[j][2], o[j][3],
                                  ah0, ah1, ah2, ah3, bv[j2 * 2], bv[j2 * 2 + 1]);
                        mma_16816(o[j][0], o[j][1], o[j][2], o[j][3],
                                  al0, al1, al2, al3, bv[j2 * 2], bv[j2 * 2 + 1]);
                    }
                    ldm_x4_t(bv[0], bv[1], bv[2], bv[3],
                             stg + 3 * KV_TERM + tb + v_lane);               // vlo
                    #pragma unroll
                    for (int j2 = 0; j2 < 2; j2++) {
                        const int j = nb * 2 + j2;
                        mma_16816(o[j][0], o[j][1], o[j][2], o[j][3],
                                  ah0, ah1, ah2, ah3, bv[j2 * 2], bv[j2 * 2 + 1]);
                    }
                }
            }
        }
        __syncthreads();
    }

    const int b = bh >> 4, head = bh & (H - 1);
    #pragma unroll
    for (int h2 = 0; h2 < 2; h2++) {
        const float inv = 1.0f / row_l[h2];
        const int row = m0w + (lane >> 2) + h2 * 8;
        #pragma unroll
        for (int j = 0; j < 8; j++) {
            const int col = head * DK + j * 8 + (lane & 3) * 2;
            const size_t idx = (size_t)(b * S + row) * D + col;
            float2 v = make_float2(o[j][h2 * 2] * inv, o[j][h2 * 2 + 1] * inv);
            __nv_bfloat162 hv = __float22bfloat162_rn(v);
            float2 hf = __bfloat1622float2(hv);
            __nv_bfloat162 lv = __float22bfloat162_rn(
                make_float2(v.x - hf.x, v.y - hf.y));
            *(__nv_bfloat162*)(g_Ahi + idx) = hv;
            *(__nv_bfloat162*)(g_Alo + idx) = lv;
        }
    }
}

// ---------------------------------------------------------------------------
extern "C" void kernel_launch(void* const* d_in, const int* in_sizes, int n_in,
                              void* d_out, int out_size)
{
    const float* Q  = (const float*)d_in[0];
    const float* K  = (const float*)d_in[1];
    const float* V  = (const float*)d_in[2];
    const float* Wq = (const float*)d_in[3];
    const float* Wk = (const float*)d_in[4];
    const float* Wv = (const float*)d_in[5];
    const float* Wo = (const float*)d_in[6];
    const float* bo = (const float*)d_in[7];
    float* out = (float*)d_out;

    (void)in_sizes; (void)n_in; (void)out_size;

    cudaFuncSetAttribute(tc_gemm_qkv,
                         cudaFuncAttributeMaxDynamicSharedMemorySize, QKV_SMEM);
    cudaFuncSetAttribute(tc_gemm_out,
                         cudaFuncAttributeMaxDynamicSharedMemorySize, GEMM_SMEM);
    cudaFuncSetAttribute(flash_attn_tc,
                         cudaFuncAttributeMaxDynamicSharedMemorySize, ATTN_SMEM);

    convert_a_kernel<<<dim3(M * D / (256 * 16), 1, 3), 256>>>(Q, K, V);
    convert_w_kernel<<<dim3(D / 32, D / 64, 4), dim3(32, 8)>>>(Wq, Wk, Wv, Wo);

    // Q/K/V projections: 128x64 tiles (1536 CTAs — low wave quantization)
    tc_gemm_qkv<<<dim3(D / 64, M / GBM, 3), 256, QKV_SMEM>>>();

    flash_attn_tc<<<dim3(S / 128, B * H), 256, ATTN_SMEM>>>();

    tc_gemm_out<<<dim3(D / GBN, M / GBM), 256, GEMM_SMEM>>>(out, bo);
}